// round 1
// baseline (speedup 1.0000x reference)
#include <cuda_runtime.h>

// Problem constants
#define NN   10000
#define NE   320000
#define IND  128
#define F1   512     // 2*HID (combined a+s hidden)
#define F2   256     // 2*OUT

// Output layout: x_ [NN*128], s_ [NN*NN], h [NN*128]
#define S_OFF  (NN * 128)
#define H_OFF  (S_OFF + (size_t)NN * NN)

// ---------------- static device scratch (no allocs allowed) ----------------
__device__ float g_XW1[NN * F1];    // h @ [W1a | W1s]
__device__ float g_H1 [NN * F1];    // relu(agg(XW1) + b1)
__device__ float g_XW2[NN * F2];    // H1 @ [W2a | W2s] (blockwise)
__device__ float g_Hs [NN * 128];   // structure embedding h_
__device__ float g_dinv[NN];
__device__ int   g_cnt[NN];
__device__ int   g_cur[NN];
__device__ int   g_rowptr[NN + 1];
__device__ int   g_col[NE];

// ---------------- graph preprocessing ----------------
__global__ void k_init() {
    int i = blockIdx.x * 256 + threadIdx.x;
    if (i < NN) { g_cnt[i] = 0; g_cur[i] = 0; }
}

__global__ void k_count(const int* __restrict__ dst) {
    int e = blockIdx.x * 256 + threadIdx.x;
    if (e < NE) atomicAdd(&g_cnt[dst[e]], 1);
}

// single-block exclusive scan over g_cnt -> g_rowptr  (NN = 10000, 1024 thr x 10)
__global__ void k_scan() {
    __shared__ int s[1024];
    int t = threadIdx.x;
    const int CH = 10;
    int base = t * CH;
    int sum = 0;
    #pragma unroll
    for (int i = 0; i < CH; i++) { int idx = base + i; if (idx < NN) sum += g_cnt[idx]; }
    s[t] = sum;
    __syncthreads();
    for (int off = 1; off < 1024; off <<= 1) {
        int v = (t >= off) ? s[t - off] : 0;
        __syncthreads();
        s[t] += v;
        __syncthreads();
    }
    int run = (t > 0) ? s[t - 1] : 0;
    #pragma unroll
    for (int i = 0; i < CH; i++) {
        int idx = base + i;
        if (idx < NN) { g_rowptr[idx] = run; run += g_cnt[idx]; }
    }
    if (t == 1023) g_rowptr[NN] = s[1023];
}

__global__ void k_dinv() {
    int i = blockIdx.x * 256 + threadIdx.x;
    if (i < NN) g_dinv[i] = rsqrtf(1.0f + (float)g_cnt[i]);   // +1 self loop
}

__global__ void k_fill(const int* __restrict__ src, const int* __restrict__ dst) {
    int e = blockIdx.x * 256 + threadIdx.x;
    if (e < NE) {
        int d = dst[e];
        int pos = g_rowptr[d] + atomicAdd(&g_cur[d], 1);
        g_col[pos] = src[e];
    }
}

// ---------------- SGEMM: C[M,N] = A[M,K] * B ----------------
// BT=false: B is [K, ldb] row-major (dense weight), N must be a multiple of 128.
// BT=true : B is [N, ldb=K] row-major (B used transposed: Gram / A@Bt).
// Block tile 128x128, BK=8, 256 threads, 8x8 microtile.
template <bool BT>
__global__ void sgemm(const float* __restrict__ A, int lda, int aoff,
                      const float* __restrict__ B, int ldb,
                      float* __restrict__ C, int ldc, int coff,
                      int M, int N, int K)
{
    __shared__ float As[8][128];
    __shared__ float Bs[8][128];

    const int tid  = threadIdx.x;
    const int m0   = blockIdx.y * 128;
    const int n0   = blockIdx.x * 128;
    const int trow = tid >> 4;        // 0..15
    const int tcol = tid & 15;        // 0..15
    const int lrow = tid >> 1;        // 0..127
    const int lk4  = (tid & 1) * 4;   // 0 or 4
    const int brow = tid >> 5;        // 0..7  (BT=false path)
    const int bcol = (tid & 31) * 4;  // 0..124

    float acc[8][8];
    #pragma unroll
    for (int i = 0; i < 8; i++)
        #pragma unroll
        for (int j = 0; j < 8; j++) acc[i][j] = 0.0f;

    for (int k0 = 0; k0 < K; k0 += 8) {
        float4 av = make_float4(0.f, 0.f, 0.f, 0.f);
        if (m0 + lrow < M)
            av = *(const float4*)&A[(size_t)(m0 + lrow) * lda + aoff + k0 + lk4];
        As[lk4 + 0][lrow] = av.x; As[lk4 + 1][lrow] = av.y;
        As[lk4 + 2][lrow] = av.z; As[lk4 + 3][lrow] = av.w;

        if (!BT) {
            float4 bv = *(const float4*)&B[(size_t)(k0 + brow) * ldb + n0 + bcol];
            *(float4*)&Bs[brow][bcol] = bv;
        } else {
            float4 bv = make_float4(0.f, 0.f, 0.f, 0.f);
            if (n0 + lrow < N)
                bv = *(const float4*)&B[(size_t)(n0 + lrow) * ldb + k0 + lk4];
            Bs[lk4 + 0][lrow] = bv.x; Bs[lk4 + 1][lrow] = bv.y;
            Bs[lk4 + 2][lrow] = bv.z; Bs[lk4 + 3][lrow] = bv.w;
        }
        __syncthreads();

        #pragma unroll
        for (int k = 0; k < 8; k++) {
            float a[8], b[8];
            *(float4*)&a[0] = *(const float4*)&As[k][trow * 4];
            *(float4*)&a[4] = *(const float4*)&As[k][64 + trow * 4];
            *(float4*)&b[0] = *(const float4*)&Bs[k][tcol * 4];
            *(float4*)&b[4] = *(const float4*)&Bs[k][64 + tcol * 4];
            #pragma unroll
            for (int i = 0; i < 8; i++)
                #pragma unroll
                for (int j = 0; j < 8; j++)
                    acc[i][j] += a[i] * b[j];
        }
        __syncthreads();
    }

    // Epilogue: rows m0 + {0,64} + trow*4 + i ; cols n0 + {0,64} + tcol*4 (float4)
    #pragma unroll
    for (int ih = 0; ih < 2; ih++)
        #pragma unroll
        for (int i = 0; i < 4; i++) {
            int row = m0 + ih * 64 + trow * 4 + i;
            if (row >= M) continue;
            #pragma unroll
            for (int jh = 0; jh < 2; jh++) {
                int col = n0 + jh * 64 + tcol * 4;
                if (BT && col >= N) continue;   // N multiple of 4 -> float4 safe
                float4 v = make_float4(acc[ih * 4 + i][jh * 4 + 0],
                                       acc[ih * 4 + i][jh * 4 + 1],
                                       acc[ih * 4 + i][jh * 4 + 2],
                                       acc[ih * 4 + i][jh * 4 + 3]);
                *(float4*)&C[(size_t)row * ldc + coff + col] = v;
            }
        }
}

// ---------------- GCN aggregation (gather, no atomics) ----------------
// One block per node; thread t owns float4 column chunk c = 4*t of XW [NN, F].
// out = sum_{s in N(n)} XW[s]*dinv[s]*dinv[n] + XW[n]*dinv[n]^2 + bias (, relu)
__global__ void k_agg(const float4* __restrict__ XW4, int F4,
                      float* __restrict__ out_lo, int ld_lo,
                      float* __restrict__ out_hi, int ld_hi,
                      const float* __restrict__ ba, const float* __restrict__ bb,
                      int halfF, int do_relu)
{
    int n = blockIdx.x;
    int t = threadIdx.x;
    float di = g_dinv[n];
    float4 x = XW4[(size_t)n * F4 + t];
    float w0 = di * di;
    float4 acc = make_float4(x.x * w0, x.y * w0, x.z * w0, x.w * w0);

    int e0 = g_rowptr[n], e1 = g_rowptr[n + 1];
    for (int e = e0; e < e1; e++) {
        int s = g_col[e];
        float ws = g_dinv[s] * di;
        float4 v = XW4[(size_t)s * F4 + t];
        acc.x += v.x * ws; acc.y += v.y * ws;
        acc.z += v.z * ws; acc.w += v.w * ws;
    }

    int c = t * 4;
    if (c < halfF) {
        float4 bv = *(const float4*)&ba[c];
        acc.x += bv.x; acc.y += bv.y; acc.z += bv.z; acc.w += bv.w;
        if (do_relu) {
            acc.x = fmaxf(acc.x, 0.f); acc.y = fmaxf(acc.y, 0.f);
            acc.z = fmaxf(acc.z, 0.f); acc.w = fmaxf(acc.w, 0.f);
        }
        *(float4*)&out_lo[(size_t)n * ld_lo + c] = acc;
    } else {
        int cc = c - halfF;
        float4 bv = *(const float4*)&bb[cc];
        acc.x += bv.x; acc.y += bv.y; acc.z += bv.z; acc.w += bv.w;
        if (do_relu) {
            acc.x = fmaxf(acc.x, 0.f); acc.y = fmaxf(acc.y, 0.f);
            acc.z = fmaxf(acc.z, 0.f); acc.w = fmaxf(acc.w, 0.f);
        }
        *(float4*)&out_hi[(size_t)n * ld_hi + cc] = acc;
    }
}

// ---------------- launcher ----------------
extern "C" void kernel_launch(void* const* d_in, const int* in_sizes, int n_in,
                              void* d_out, int out_size)
{
    const float* h   = (const float*)d_in[0];
    const float* W1a = (const float*)d_in[1];
    const float* b1a = (const float*)d_in[2];
    const float* W2a = (const float*)d_in[3];
    const float* b2a = (const float*)d_in[4];
    const float* W1s = (const float*)d_in[5];
    const float* b1s = (const float*)d_in[6];
    const float* W2s = (const float*)d_in[7];
    const float* b2s = (const float*)d_in[8];
    const int*   ei  = (const int*)d_in[9];
    const int* src = ei;
    const int* dst = ei + NE;
    float* out = (float*)d_out;

    float *pXW1, *pH1, *pXW2, *pHs;
    cudaGetSymbolAddress((void**)&pXW1, g_XW1);
    cudaGetSymbolAddress((void**)&pH1,  g_H1);
    cudaGetSymbolAddress((void**)&pXW2, g_XW2);
    cudaGetSymbolAddress((void**)&pHs,  g_Hs);

    // graph prep
    k_init <<<(NN + 255) / 256, 256>>>();
    k_count<<<(NE + 255) / 256, 256>>>(dst);
    k_scan <<<1, 1024>>>();
    k_dinv <<<(NN + 255) / 256, 256>>>();
    k_fill <<<(NE + 255) / 256, 256>>>(src, dst);

    const int MB = (NN + 127) / 128;   // 79

    // layer 1: XW1 = h @ [W1a | W1s]   (N, 512)
    sgemm<false><<<dim3(2, MB), 256>>>(h, IND, 0, W1a, 256, pXW1, F1, 0,   NN, 256, IND);
    sgemm<false><<<dim3(2, MB), 256>>>(h, IND, 0, W1s, 256, pXW1, F1, 256, NN, 256, IND);
    // aggregate + bias + relu -> H1
    k_agg<<<NN, F1 / 4>>>((const float4*)pXW1, F1 / 4,
                          pH1, F1, pH1 + 256, F1, b1a, b1s, 256, 1);

    // layer 2: XW2[:, :128] = H1[:, :256] @ W2a ; XW2[:,128:] = H1[:,256:] @ W2s
    sgemm<false><<<dim3(1, MB), 256>>>(pH1, F1, 0,   W2a, 128, pXW2, F2, 0,   NN, 128, 256);
    sgemm<false><<<dim3(1, MB), 256>>>(pH1, F1, 256, W2s, 128, pXW2, F2, 128, NN, 128, 256);
    // aggregate + bias -> x_ (directly into out) and h_ (g_Hs)
    k_agg<<<NN, F2 / 4>>>((const float4*)pXW2, F2 / 4,
                          out, 128, pHs, 128, b2a, b2s, 128, 0);

    // s_ = h_ @ h_^T  (Gram), written at out + S_OFF
    sgemm<true><<<dim3(MB, MB), 256>>>(pHs, 128, 0, pHs, 128,
                                       out + S_OFF, NN, 0, NN, NN, 128);

    // h passthrough
    cudaMemcpyAsync(out + H_OFF, h, (size_t)NN * 128 * sizeof(float),
                    cudaMemcpyDeviceToDevice);
}

// round 3
// speedup vs baseline: 1.8057x; 1.8057x over previous
#include <cuda_runtime.h>
#include <cuda_bf16.h>
#include <cstdint>

// Problem constants
#define NN   10000
#define NE   320000
#define IND  128
#define F1   512     // 2*HID (combined a+s hidden)
#define F2   256     // 2*OUT

// Output layout: x_ [NN*128], s_ [NN*NN], h [NN*128]
#define S_OFF  (NN * 128)
#define H_OFF  (S_OFF + (size_t)NN * NN)

// ---------------- static device scratch (no allocs allowed) ----------------
__device__ float g_XW1[NN * F1];          // h @ [W1a | W1s]
__device__ float g_H1 [NN * F1];          // relu(agg(XW1) + b1)
__device__ float g_XW2[NN * F2];          // H1 @ [W2a | W2s]
__device__ __nv_bfloat16 g_Hb[NN * 256];  // h_ split: cols [0,128)=hi, [128,256)=lo
__device__ float g_dinv[NN];
__device__ int   g_cnt[NN];
__device__ int   g_cur[NN];
__device__ int   g_rowptr[NN + 1];
__device__ int   g_col[NE];

// ---------------- graph preprocessing ----------------
__global__ void k_init() {
    int i = blockIdx.x * 256 + threadIdx.x;
    if (i < NN) { g_cnt[i] = 0; g_cur[i] = 0; }
}

__global__ void k_count(const int* __restrict__ dst) {
    int e = blockIdx.x * 256 + threadIdx.x;
    if (e < NE) atomicAdd(&g_cnt[dst[e]], 1);
}

// single-block exclusive scan over g_cnt -> g_rowptr  (NN = 10000, 1024 thr x 10)
__global__ void k_scan() {
    __shared__ int s[1024];
    int t = threadIdx.x;
    const int CH = 10;
    int base = t * CH;
    int sum = 0;
    #pragma unroll
    for (int i = 0; i < CH; i++) { int idx = base + i; if (idx < NN) sum += g_cnt[idx]; }
    s[t] = sum;
    __syncthreads();
    for (int off = 1; off < 1024; off <<= 1) {
        int v = (t >= off) ? s[t - off] : 0;
        __syncthreads();
        s[t] += v;
        __syncthreads();
    }
    int run = (t > 0) ? s[t - 1] : 0;
    #pragma unroll
    for (int i = 0; i < CH; i++) {
        int idx = base + i;
        if (idx < NN) { g_rowptr[idx] = run; run += g_cnt[idx]; }
    }
    if (t == 1023) g_rowptr[NN] = s[1023];
}

__global__ void k_dinv() {
    int i = blockIdx.x * 256 + threadIdx.x;
    if (i < NN) g_dinv[i] = rsqrtf(1.0f + (float)g_cnt[i]);   // +1 self loop
}

__global__ void k_fill(const int* __restrict__ src, const int* __restrict__ dst) {
    int e = blockIdx.x * 256 + threadIdx.x;
    if (e < NE) {
        int d = dst[e];
        int pos = g_rowptr[d] + atomicAdd(&g_cur[d], 1);
        g_col[pos] = src[e];
    }
}

// ---------------- SGEMM (weights path): C[M,N] = A[M,K] * B[K,N] ----------------
__global__ void sgemm(const float* __restrict__ A, int lda, int aoff,
                      const float* __restrict__ B, int ldb,
                      float* __restrict__ C, int ldc, int coff,
                      int M, int N, int K)
{
    __shared__ float As[8][128];
    __shared__ float Bs[8][128];

    const int tid  = threadIdx.x;
    const int m0   = blockIdx.y * 128;
    const int n0   = blockIdx.x * 128;
    const int trow = tid >> 4;
    const int tcol = tid & 15;
    const int lrow = tid >> 1;
    const int lk4  = (tid & 1) * 4;
    const int brow = tid >> 5;
    const int bcol = (tid & 31) * 4;

    float acc[8][8];
    #pragma unroll
    for (int i = 0; i < 8; i++)
        #pragma unroll
        for (int j = 0; j < 8; j++) acc[i][j] = 0.0f;

    for (int k0 = 0; k0 < K; k0 += 8) {
        float4 av = make_float4(0.f, 0.f, 0.f, 0.f);
        if (m0 + lrow < M)
            av = *(const float4*)&A[(size_t)(m0 + lrow) * lda + aoff + k0 + lk4];
        As[lk4 + 0][lrow] = av.x; As[lk4 + 1][lrow] = av.y;
        As[lk4 + 2][lrow] = av.z; As[lk4 + 3][lrow] = av.w;

        float4 bv = *(const float4*)&B[(size_t)(k0 + brow) * ldb + n0 + bcol];
        *(float4*)&Bs[brow][bcol] = bv;
        __syncthreads();

        #pragma unroll
        for (int k = 0; k < 8; k++) {
            float a[8], b[8];
            *(float4*)&a[0] = *(const float4*)&As[k][trow * 4];
            *(float4*)&a[4] = *(const float4*)&As[k][64 + trow * 4];
            *(float4*)&b[0] = *(const float4*)&Bs[k][tcol * 4];
            *(float4*)&b[4] = *(const float4*)&Bs[k][64 + tcol * 4];
            #pragma unroll
            for (int i = 0; i < 8; i++)
                #pragma unroll
                for (int j = 0; j < 8; j++)
                    acc[i][j] += a[i] * b[j];
        }
        __syncthreads();
    }

    #pragma unroll
    for (int ih = 0; ih < 2; ih++)
        #pragma unroll
        for (int i = 0; i < 4; i++) {
            int row = m0 + ih * 64 + trow * 4 + i;
            if (row >= M) continue;
            #pragma unroll
            for (int jh = 0; jh < 2; jh++) {
                int col = n0 + jh * 64 + tcol * 4;
                float4 v = make_float4(acc[ih * 4 + i][jh * 4 + 0],
                                       acc[ih * 4 + i][jh * 4 + 1],
                                       acc[ih * 4 + i][jh * 4 + 2],
                                       acc[ih * 4 + i][jh * 4 + 3]);
                *(float4*)&C[(size_t)row * ldc + coff + col] = v;
            }
        }
}

// ---------------- GCN aggregation layer 1 (gather, no atomics) ----------------
__global__ void k_agg(const float4* __restrict__ XW4, int F4,
                      float* __restrict__ out_lo, int ld_lo,
                      float* __restrict__ out_hi, int ld_hi,
                      const float* __restrict__ ba, const float* __restrict__ bb,
                      int halfF, int do_relu)
{
    int n = blockIdx.x;
    int t = threadIdx.x;
    float di = g_dinv[n];
    float4 x = XW4[(size_t)n * F4 + t];
    float w0 = di * di;
    float4 acc = make_float4(x.x * w0, x.y * w0, x.z * w0, x.w * w0);

    int e0 = g_rowptr[n], e1 = g_rowptr[n + 1];
    for (int e = e0; e < e1; e++) {
        int s = g_col[e];
        float ws = g_dinv[s] * di;
        float4 v = XW4[(size_t)s * F4 + t];
        acc.x += v.x * ws; acc.y += v.y * ws;
        acc.z += v.z * ws; acc.w += v.w * ws;
    }

    int c = t * 4;
    if (c < halfF) {
        float4 bv = *(const float4*)&ba[c];
        acc.x += bv.x; acc.y += bv.y; acc.z += bv.z; acc.w += bv.w;
        if (do_relu) {
            acc.x = fmaxf(acc.x, 0.f); acc.y = fmaxf(acc.y, 0.f);
            acc.z = fmaxf(acc.z, 0.f); acc.w = fmaxf(acc.w, 0.f);
        }
        *(float4*)&out_lo[(size_t)n * ld_lo + c] = acc;
    } else {
        int cc = c - halfF;
        float4 bv = *(const float4*)&bb[cc];
        acc.x += bv.x; acc.y += bv.y; acc.z += bv.z; acc.w += bv.w;
        if (do_relu) {
            acc.x = fmaxf(acc.x, 0.f); acc.y = fmaxf(acc.y, 0.f);
            acc.z = fmaxf(acc.z, 0.f); acc.w = fmaxf(acc.w, 0.f);
        }
        *(float4*)&out_hi[(size_t)n * ld_hi + cc] = acc;
    }
}

// ---------------- GCN aggregation layer 2: x_ (fp32) + h_ (split bf16) ----------
struct alignas(8) bf4 { __nv_bfloat162 a, b; };

__global__ void k_agg2(const float4* __restrict__ XW4,   // [NN][64] float4 (F2=256)
                       float* __restrict__ xout,          // [NN][128]
                       __nv_bfloat16* __restrict__ Hb,    // [NN][256] hi|lo
                       const float* __restrict__ b2a, const float* __restrict__ b2s)
{
    int n = blockIdx.x;
    int t = threadIdx.x;   // 64 threads
    float di = g_dinv[n];
    float4 x = XW4[(size_t)n * 64 + t];
    float w0 = di * di;
    float4 acc = make_float4(x.x * w0, x.y * w0, x.z * w0, x.w * w0);

    int e0 = g_rowptr[n], e1 = g_rowptr[n + 1];
    for (int e = e0; e < e1; e++) {
        int s = g_col[e];
        float ws = g_dinv[s] * di;
        float4 v = XW4[(size_t)s * 64 + t];
        acc.x += v.x * ws; acc.y += v.y * ws;
        acc.z += v.z * ws; acc.w += v.w * ws;
    }

    int c = t * 4;
    if (c < 128) {
        float4 bv = *(const float4*)&b2a[c];
        acc.x += bv.x; acc.y += bv.y; acc.z += bv.z; acc.w += bv.w;
        *(float4*)&xout[(size_t)n * 128 + c] = acc;
    } else {
        int cc = c - 128;
        float4 bv = *(const float4*)&b2s[cc];
        acc.x += bv.x; acc.y += bv.y; acc.z += bv.z; acc.w += bv.w;
        __nv_bfloat16 h0 = __float2bfloat16(acc.x);
        __nv_bfloat16 h1 = __float2bfloat16(acc.y);
        __nv_bfloat16 h2 = __float2bfloat16(acc.z);
        __nv_bfloat16 h3 = __float2bfloat16(acc.w);
        __nv_bfloat16 l0 = __float2bfloat16(acc.x - __bfloat162float(h0));
        __nv_bfloat16 l1 = __float2bfloat16(acc.y - __bfloat162float(h1));
        __nv_bfloat16 l2 = __float2bfloat16(acc.z - __bfloat162float(h2));
        __nv_bfloat16 l3 = __float2bfloat16(acc.w - __bfloat162float(h3));
        bf4 hv; hv.a = __nv_bfloat162(h0, h1); hv.b = __nv_bfloat162(h2, h3);
        bf4 lv; lv.a = __nv_bfloat162(l0, l1); lv.b = __nv_bfloat162(l2, l3);
        *(bf4*)&Hb[(size_t)n * 256 + cc]       = hv;
        *(bf4*)&Hb[(size_t)n * 256 + 128 + cc] = lv;
    }
}

// ---------------- Gram via bf16 tensor cores ----------------
// C[NN,NN] = Hb @ Hb^T over K=256 (split-bf16 => ~fp32 accuracy), fp32 accum.
// Block tile 128x128, 8 warps (2x4, 64x32 warp tiles), BK=32 double-buffered cp.async.
#define BK 32
#define SP 40   // smem row pitch in bf16 (80B: conflict-free for ldmatrix)

__global__ void __launch_bounds__(256)
gram_mma(const __nv_bfloat16* __restrict__ Hb, float* __restrict__ C)
{
    __shared__ __align__(16) __nv_bfloat16 As[2][128 * SP];
    __shared__ __align__(16) __nv_bfloat16 Bs[2][128 * SP];

    const int tid  = threadIdx.x;
    const int m0   = blockIdx.y * 128;
    const int n0   = blockIdx.x * 128;
    const int w    = tid >> 5;
    const int lane = tid & 31;
    const int wm   = w >> 2;   // 0..1
    const int wn   = w & 3;    // 0..3

    float acc[4][4][4];
    #pragma unroll
    for (int mt = 0; mt < 4; mt++)
        #pragma unroll
        for (int nt = 0; nt < 4; nt++)
            #pragma unroll
            for (int i = 0; i < 4; i++) acc[mt][nt][i] = 0.0f;

    auto load_stage = [&](int kc, int st) {
        #pragma unroll
        for (int i = 0; i < 2; i++) {
            int c = tid + i * 256;            // 0..511
            int r = c >> 2, q = c & 3;        // row, 16B-chunk
            // A tile
            {
                int grow = m0 + r;
                int rg = grow < NN ? grow : NN - 1;
                const __nv_bfloat16* src = Hb + (size_t)rg * 256 + kc * BK + q * 8;
                uint32_t dst = (uint32_t)__cvta_generic_to_shared(&As[st][r * SP + q * 8]);
                int sz = grow < NN ? 16 : 0;
                asm volatile("cp.async.cg.shared.global [%0], [%1], 16, %2;\n"
                             :: "r"(dst), "l"(src), "r"(sz));
            }
            // B tile
            {
                int grow = n0 + r;
                int rg = grow < NN ? grow : NN - 1;
                const __nv_bfloat16* src = Hb + (size_t)rg * 256 + kc * BK + q * 8;
                uint32_t dst = (uint32_t)__cvta_generic_to_shared(&Bs[st][r * SP + q * 8]);
                int sz = grow < NN ? 16 : 0;
                asm volatile("cp.async.cg.shared.global [%0], [%1], 16, %2;\n"
                             :: "r"(dst), "l"(src), "r"(sz));
            }
        }
    };

    auto compute = [&](int st) {
        #pragma unroll
        for (int ks = 0; ks < 2; ks++) {
            uint32_t a[4][4];
            #pragma unroll
            for (int mt = 0; mt < 4; mt++) {
                int row = wm * 64 + mt * 16 + (lane & 15);
                int col = ks * 16 + ((lane >> 4) << 3);
                uint32_t ad = (uint32_t)__cvta_generic_to_shared(&As[st][row * SP + col]);
                asm volatile("ldmatrix.sync.aligned.m8n8.x4.shared.b16 {%0,%1,%2,%3}, [%4];"
                             : "=r"(a[mt][0]), "=r"(a[mt][1]), "=r"(a[mt][2]), "=r"(a[mt][3])
                             : "r"(ad));
            }
            uint32_t b[2][4];
            #pragma unroll
            for (int p = 0; p < 2; p++) {
                int j = lane >> 3, l = lane & 7;
                int row = wn * 32 + p * 16 + ((j >> 1) << 3) + l;
                int col = ks * 16 + ((j & 1) << 3);
                uint32_t bd = (uint32_t)__cvta_generic_to_shared(&Bs[st][row * SP + col]);
                asm volatile("ldmatrix.sync.aligned.m8n8.x4.shared.b16 {%0,%1,%2,%3}, [%4];"
                             : "=r"(b[p][0]), "=r"(b[p][1]), "=r"(b[p][2]), "=r"(b[p][3])
                             : "r"(bd));
            }
            #pragma unroll
            for (int mt = 0; mt < 4; mt++)
                #pragma unroll
                for (int nt = 0; nt < 4; nt++) {
                    uint32_t b0 = b[nt >> 1][(nt & 1) * 2];
                    uint32_t b1 = b[nt >> 1][(nt & 1) * 2 + 1];
                    asm volatile(
                        "mma.sync.aligned.m16n8k16.row.col.f32.bf16.bf16.f32 "
                        "{%0,%1,%2,%3}, {%4,%5,%6,%7}, {%8,%9}, {%0,%1,%2,%3};"
                        : "+f"(acc[mt][nt][0]), "+f"(acc[mt][nt][1]),
                          "+f"(acc[mt][nt][2]), "+f"(acc[mt][nt][3])
                        : "r"(a[mt][0]), "r"(a[mt][1]), "r"(a[mt][2]), "r"(a[mt][3]),
                          "r"(b0), "r"(b1));
                }
        }
    };

    load_stage(0, 0);
    asm volatile("cp.async.commit_group;");

    #pragma unroll 1
    for (int kc = 0; kc < 8; kc++) {
        if (kc < 7) {
            load_stage(kc + 1, (kc + 1) & 1);
            asm volatile("cp.async.commit_group;");
            asm volatile("cp.async.wait_group 1;");
        } else {
            asm volatile("cp.async.wait_group 0;");
        }
        __syncthreads();
        compute(kc & 1);
        __syncthreads();
    }

    // epilogue
    #pragma unroll
    for (int mt = 0; mt < 4; mt++)
        #pragma unroll
        for (int nt = 0; nt < 4; nt++) {
            int row = m0 + wm * 64 + mt * 16 + (lane >> 2);
            int col = n0 + wn * 32 + nt * 8 + (lane & 3) * 2;
            if (col < NN) {
                if (row < NN)
                    *(float2*)&C[(size_t)row * NN + col] =
                        make_float2(acc[mt][nt][0], acc[mt][nt][1]);
                if (row + 8 < NN)
                    *(float2*)&C[(size_t)(row + 8) * NN + col] =
                        make_float2(acc[mt][nt][2], acc[mt][nt][3]);
            }
        }
}

// ---------------- launcher ----------------
extern "C" void kernel_launch(void* const* d_in, const int* in_sizes, int n_in,
                              void* d_out, int out_size)
{
    const float* h   = (const float*)d_in[0];
    const float* W1a = (const float*)d_in[1];
    const float* b1a = (const float*)d_in[2];
    const float* W2a = (const float*)d_in[3];
    const float* b2a = (const float*)d_in[4];
    const float* W1s = (const float*)d_in[5];
    const float* b1s = (const float*)d_in[6];
    const float* W2s = (const float*)d_in[7];
    const float* b2s = (const float*)d_in[8];
    const int*   ei  = (const int*)d_in[9];
    const int* src = ei;
    const int* dst = ei + NE;
    float* out = (float*)d_out;

    float *pXW1, *pH1, *pXW2;
    __nv_bfloat16* pHb;
    cudaGetSymbolAddress((void**)&pXW1, g_XW1);
    cudaGetSymbolAddress((void**)&pH1,  g_H1);
    cudaGetSymbolAddress((void**)&pXW2, g_XW2);
    cudaGetSymbolAddress((void**)&pHb,  g_Hb);

    // graph prep
    k_init <<<(NN + 255) / 256, 256>>>();
    k_count<<<(NE + 255) / 256, 256>>>(dst);
    k_scan <<<1, 1024>>>();
    k_dinv <<<(NN + 255) / 256, 256>>>();
    k_fill <<<(NE + 255) / 256, 256>>>(src, dst);

    const int MB = (NN + 127) / 128;   // 79

    // layer 1: XW1 = h @ [W1a | W1s]   (N, 512)
    sgemm<<<dim3(2, MB), 256>>>(h, IND, 0, W1a, 256, pXW1, F1, 0,   NN, 256, IND);
    sgemm<<<dim3(2, MB), 256>>>(h, IND, 0, W1s, 256, pXW1, F1, 256, NN, 256, IND);
    k_agg<<<NN, F1 / 4>>>((const float4*)pXW1, F1 / 4,
                          pH1, F1, pH1 + 256, F1, b1a, b1s, 256, 1);

    // layer 2
    sgemm<<<dim3(1, MB), 256>>>(pH1, F1, 0,   W2a, 128, pXW2, F2, 0,   NN, 128, 256);
    sgemm<<<dim3(1, MB), 256>>>(pH1, F1, 256, W2s, 128, pXW2, F2, 128, NN, 128, 256);
    k_agg2<<<NN, 64>>>((const float4*)pXW2, out, pHb, b2a, b2s);

    // s_ = h_ @ h_^T via bf16 tensor cores (split compensation, K=256)
    gram_mma<<<dim3(MB, MB), 256>>>(pHb, out + S_OFF);

    // h passthrough
    cudaMemcpyAsync(out + H_OFF, h, (size_t)NN * 128 * sizeof(float),
                    cudaMemcpyDeviceToDevice);
}

// round 5
// speedup vs baseline: 1.8752x; 1.0385x over previous
#include <cuda_runtime.h>
#include <cuda_bf16.h>
#include <cstdint>

// Problem constants
#define NN   10000
#define NE   320000
#define IND  128
#define F1   512     // 2*HID (combined a+s hidden)
#define F2   256     // 2*OUT

// Output layout: x_ [NN*128], s_ [NN*NN], h [NN*128]
#define S_OFF  (NN * 128)
#define H_OFF  (S_OFF + (size_t)NN * NN)

// ---------------- static device scratch (no allocs allowed) ----------------
__device__ float g_XW1[NN * F1];          // h @ [W1a | W1s]
__device__ float g_H1 [NN * F1];          // relu(agg(XW1) + b1)
__device__ float g_XW2[NN * F2];          // H1 @ [W2a | W2s]
__device__ __nv_bfloat16 g_Hb[NN * 256];  // h_ split: cols [0,128)=hi, [128,256)=lo
__device__ float g_dinv[NN];
__device__ int   g_cnt[NN];
__device__ int   g_cur[NN];
__device__ int   g_rowptr[NN + 1];
__device__ int   g_col[NE];

// ---------------- graph preprocessing ----------------
__global__ void k_init() {
    int i = blockIdx.x * 256 + threadIdx.x;
    if (i < NN) { g_cnt[i] = 0; g_cur[i] = 0; }
}

__global__ void k_count(const int* __restrict__ dst) {
    int e = blockIdx.x * 256 + threadIdx.x;
    if (e < NE) atomicAdd(&g_cnt[dst[e]], 1);
}

__global__ void k_scan() {
    __shared__ int s[1024];
    int t = threadIdx.x;
    const int CH = 10;
    int base = t * CH;
    int sum = 0;
    #pragma unroll
    for (int i = 0; i < CH; i++) { int idx = base + i; if (idx < NN) sum += g_cnt[idx]; }
    s[t] = sum;
    __syncthreads();
    for (int off = 1; off < 1024; off <<= 1) {
        int v = (t >= off) ? s[t - off] : 0;
        __syncthreads();
        s[t] += v;
        __syncthreads();
    }
    int run = (t > 0) ? s[t - 1] : 0;
    #pragma unroll
    for (int i = 0; i < CH; i++) {
        int idx = base + i;
        if (idx < NN) { g_rowptr[idx] = run; run += g_cnt[idx]; }
    }
    if (t == 1023) g_rowptr[NN] = s[1023];
}

__global__ void k_dinv() {
    int i = blockIdx.x * 256 + threadIdx.x;
    if (i < NN) g_dinv[i] = rsqrtf(1.0f + (float)g_cnt[i]);   // +1 self loop
}

__global__ void k_fill(const int* __restrict__ src, const int* __restrict__ dst) {
    int e = blockIdx.x * 256 + threadIdx.x;
    if (e < NE) {
        int d = dst[e];
        int pos = g_rowptr[d] + atomicAdd(&g_cur[d], 1);
        g_col[pos] = src[e];
    }
}

// ---------------- SGEMM (weights path): C[M,N] = A[M,K] * B[K,N] ----------------
__global__ void sgemm(const float* __restrict__ A, int lda, int aoff,
                      const float* __restrict__ B, int ldb,
                      float* __restrict__ C, int ldc, int coff,
                      int M, int N, int K)
{
    __shared__ float As[8][128];
    __shared__ float Bs[8][128];

    const int tid  = threadIdx.x;
    const int m0   = blockIdx.y * 128;
    const int n0   = blockIdx.x * 128;
    const int trow = tid >> 4;
    const int tcol = tid & 15;
    const int lrow = tid >> 1;
    const int lk4  = (tid & 1) * 4;
    const int brow = tid >> 5;
    const int bcol = (tid & 31) * 4;

    float acc[8][8];
    #pragma unroll
    for (int i = 0; i < 8; i++)
        #pragma unroll
        for (int j = 0; j < 8; j++) acc[i][j] = 0.0f;

    for (int k0 = 0; k0 < K; k0 += 8) {
        float4 av = make_float4(0.f, 0.f, 0.f, 0.f);
        if (m0 + lrow < M)
            av = *(const float4*)&A[(size_t)(m0 + lrow) * lda + aoff + k0 + lk4];
        As[lk4 + 0][lrow] = av.x; As[lk4 + 1][lrow] = av.y;
        As[lk4 + 2][lrow] = av.z; As[lk4 + 3][lrow] = av.w;

        float4 bv = *(const float4*)&B[(size_t)(k0 + brow) * ldb + n0 + bcol];
        *(float4*)&Bs[brow][bcol] = bv;
        __syncthreads();

        #pragma unroll
        for (int k = 0; k < 8; k++) {
            float a[8], b[8];
            *(float4*)&a[0] = *(const float4*)&As[k][trow * 4];
            *(float4*)&a[4] = *(const float4*)&As[k][64 + trow * 4];
            *(float4*)&b[0] = *(const float4*)&Bs[k][tcol * 4];
            *(float4*)&b[4] = *(const float4*)&Bs[k][64 + tcol * 4];
            #pragma unroll
            for (int i = 0; i < 8; i++)
                #pragma unroll
                for (int j = 0; j < 8; j++)
                    acc[i][j] += a[i] * b[j];
        }
        __syncthreads();
    }

    #pragma unroll
    for (int ih = 0; ih < 2; ih++)
        #pragma unroll
        for (int i = 0; i < 4; i++) {
            int row = m0 + ih * 64 + trow * 4 + i;
            if (row >= M) continue;
            #pragma unroll
            for (int jh = 0; jh < 2; jh++) {
                int col = n0 + jh * 64 + tcol * 4;
                float4 v = make_float4(acc[ih * 4 + i][jh * 4 + 0],
                                       acc[ih * 4 + i][jh * 4 + 1],
                                       acc[ih * 4 + i][jh * 4 + 2],
                                       acc[ih * 4 + i][jh * 4 + 3]);
                *(float4*)&C[(size_t)row * ldc + coff + col] = v;
            }
        }
}

// ---------------- GCN aggregation layer 1 (gather, no atomics) ----------------
__global__ void k_agg(const float4* __restrict__ XW4, int F4,
                      float* __restrict__ out_lo, int ld_lo,
                      float* __restrict__ out_hi, int ld_hi,
                      const float* __restrict__ ba, const float* __restrict__ bb,
                      int halfF, int do_relu)
{
    int n = blockIdx.x;
    int t = threadIdx.x;
    float di = g_dinv[n];
    float4 x = XW4[(size_t)n * F4 + t];
    float w0 = di * di;
    float4 acc = make_float4(x.x * w0, x.y * w0, x.z * w0, x.w * w0);

    int e0 = g_rowptr[n], e1 = g_rowptr[n + 1];
    for (int e = e0; e < e1; e++) {
        int s = g_col[e];
        float ws = g_dinv[s] * di;
        float4 v = XW4[(size_t)s * F4 + t];
        acc.x += v.x * ws; acc.y += v.y * ws;
        acc.z += v.z * ws; acc.w += v.w * ws;
    }

    int c = t * 4;
    if (c < halfF) {
        float4 bv = *(const float4*)&ba[c];
        acc.x += bv.x; acc.y += bv.y; acc.z += bv.z; acc.w += bv.w;
        if (do_relu) {
            acc.x = fmaxf(acc.x, 0.f); acc.y = fmaxf(acc.y, 0.f);
            acc.z = fmaxf(acc.z, 0.f); acc.w = fmaxf(acc.w, 0.f);
        }
        *(float4*)&out_lo[(size_t)n * ld_lo + c] = acc;
    } else {
        int cc = c - halfF;
        float4 bv = *(const float4*)&bb[cc];
        acc.x += bv.x; acc.y += bv.y; acc.z += bv.z; acc.w += bv.w;
        if (do_relu) {
            acc.x = fmaxf(acc.x, 0.f); acc.y = fmaxf(acc.y, 0.f);
            acc.z = fmaxf(acc.z, 0.f); acc.w = fmaxf(acc.w, 0.f);
        }
        *(float4*)&out_hi[(size_t)n * ld_hi + cc] = acc;
    }
}

// ---------------- GCN aggregation layer 2: x_ (fp32) + h_ (split bf16) ----------
struct alignas(8) bf4 { __nv_bfloat162 a, b; };

__global__ void k_agg2(const float4* __restrict__ XW4,   // [NN][64] float4 (F2=256)
                       float* __restrict__ xout,          // [NN][128]
                       __nv_bfloat16* __restrict__ Hb,    // [NN][256] hi|lo
                       const float* __restrict__ b2a, const float* __restrict__ b2s)
{
    int n = blockIdx.x;
    int t = threadIdx.x;   // 64 threads
    float di = g_dinv[n];
    float4 x = XW4[(size_t)n * 64 + t];
    float w0 = di * di;
    float4 acc = make_float4(x.x * w0, x.y * w0, x.z * w0, x.w * w0);

    int e0 = g_rowptr[n], e1 = g_rowptr[n + 1];
    for (int e = e0; e < e1; e++) {
        int s = g_col[e];
        float ws = g_dinv[s] * di;
        float4 v = XW4[(size_t)s * 64 + t];
        acc.x += v.x * ws; acc.y += v.y * ws;
        acc.z += v.z * ws; acc.w += v.w * ws;
    }

    int c = t * 4;
    if (c < 128) {
        float4 bv = *(const float4*)&b2a[c];
        acc.x += bv.x; acc.y += bv.y; acc.z += bv.z; acc.w += bv.w;
        *(float4*)&xout[(size_t)n * 128 + c] = acc;
    } else {
        int cc = c - 128;
        float4 bv = *(const float4*)&b2s[cc];
        acc.x += bv.x; acc.y += bv.y; acc.z += bv.z; acc.w += bv.w;
        __nv_bfloat16 h0 = __float2bfloat16(acc.x);
        __nv_bfloat16 h1 = __float2bfloat16(acc.y);
        __nv_bfloat16 h2 = __float2bfloat16(acc.z);
        __nv_bfloat16 h3 = __float2bfloat16(acc.w);
        __nv_bfloat16 l0 = __float2bfloat16(acc.x - __bfloat162float(h0));
        __nv_bfloat16 l1 = __float2bfloat16(acc.y - __bfloat162float(h1));
        __nv_bfloat16 l2 = __float2bfloat16(acc.z - __bfloat162float(h2));
        __nv_bfloat16 l3 = __float2bfloat16(acc.w - __bfloat162float(h3));
        bf4 hv; hv.a = __nv_bfloat162(h0, h1); hv.b = __nv_bfloat162(h2, h3);
        bf4 lv; lv.a = __nv_bfloat162(l0, l1); lv.b = __nv_bfloat162(l2, l3);
        *(bf4*)&Hb[(size_t)n * 256 + cc]       = hv;
        *(bf4*)&Hb[(size_t)n * 256 + 128 + cc] = lv;
    }
}

// ---------------- Gram via bf16 tensor cores (mma.sync) ----------------
// C[NN,NN] = Hb @ Hb^T over K=256 (split-bf16 => ~fp32 accuracy), fp32 accum.
// Block tile 128x128, 8 warps (2x4, 64x32 warp tiles), BK=32,
// 3-stage cp.async pipeline, ONE __syncthreads per K-chunk, 2 CTAs/SM.
#define BK 32
#define SP 40                       // smem row pitch in bf16 (80B)
#define STG_ELE (128 * SP)          // bf16 elements per tile stage
#define GRAM_SMEM (3 * 2 * STG_ELE * 2)   // 61440 bytes

__global__ void __launch_bounds__(256, 2)
gram_mma(const __nv_bfloat16* __restrict__ Hb, float* __restrict__ C)
{
    extern __shared__ __align__(16) __nv_bfloat16 smem[];
    __nv_bfloat16* As = smem;                 // [3][STG_ELE]
    __nv_bfloat16* Bs = smem + 3 * STG_ELE;   // [3][STG_ELE]

    const int tid  = threadIdx.x;
    const int m0   = blockIdx.y * 128;
    const int n0   = blockIdx.x * 128;
    const int w    = tid >> 5;
    const int lane = tid & 31;
    const int wm   = w >> 2;   // 0..1
    const int wn   = w & 3;    // 0..3

    float acc[4][4][4];
    #pragma unroll
    for (int mt = 0; mt < 4; mt++)
        #pragma unroll
        for (int nt = 0; nt < 4; nt++)
            #pragma unroll
            for (int i = 0; i < 4; i++) acc[mt][nt][i] = 0.0f;

    auto load_stage = [&](int kc, int st) {
        #pragma unroll
        for (int i = 0; i < 2; i++) {
            int c = tid + i * 256;            // 0..511
            int r = c >> 2, q = c & 3;        // row, 16B-chunk
            {
                int grow = m0 + r;
                int rg = grow < NN ? grow : NN - 1;
                const __nv_bfloat16* src = Hb + (size_t)rg * 256 + kc * BK + q * 8;
                uint32_t dst = (uint32_t)__cvta_generic_to_shared(&As[st * STG_ELE + r * SP + q * 8]);
                int sz = grow < NN ? 16 : 0;
                asm volatile("cp.async.cg.shared.global [%0], [%1], 16, %2;\n"
                             :: "r"(dst), "l"(src), "r"(sz));
            }
            {
                int grow = n0 + r;
                int rg = grow < NN ? grow : NN - 1;
                const __nv_bfloat16* src = Hb + (size_t)rg * 256 + kc * BK + q * 8;
                uint32_t dst = (uint32_t)__cvta_generic_to_shared(&Bs[st * STG_ELE + r * SP + q * 8]);
                int sz = grow < NN ? 16 : 0;
                asm volatile("cp.async.cg.shared.global [%0], [%1], 16, %2;\n"
                             :: "r"(dst), "l"(src), "r"(sz));
            }
        }
    };

    auto compute = [&](int st) {
        #pragma unroll
        for (int ks = 0; ks < 2; ks++) {
            uint32_t a[4][4];
            #pragma unroll
            for (int mt = 0; mt < 4; mt++) {
                int row = wm * 64 + mt * 16 + (lane & 15);
                int col = ks * 16 + ((lane >> 4) << 3);
                uint32_t ad = (uint32_t)__cvta_generic_to_shared(&As[st * STG_ELE + row * SP + col]);
                asm volatile("ldmatrix.sync.aligned.m8n8.x4.shared.b16 {%0,%1,%2,%3}, [%4];"
                             : "=r"(a[mt][0]), "=r"(a[mt][1]), "=r"(a[mt][2]), "=r"(a[mt][3])
                             : "r"(ad));
            }
            uint32_t b[2][4];
            #pragma unroll
            for (int p = 0; p < 2; p++) {
                int j = lane >> 3, l = lane & 7;
                int row = wn * 32 + p * 16 + ((j >> 1) << 3) + l;
                int col = ks * 16 + ((j & 1) << 3);
                uint32_t bd = (uint32_t)__cvta_generic_to_shared(&Bs[st * STG_ELE + row * SP + col]);
                asm volatile("ldmatrix.sync.aligned.m8n8.x4.shared.b16 {%0,%1,%2,%3}, [%4];"
                             : "=r"(b[p][0]), "=r"(b[p][1]), "=r"(b[p][2]), "=r"(b[p][3])
                             : "r"(bd));
            }
            #pragma unroll
            for (int mt = 0; mt < 4; mt++)
                #pragma unroll
                for (int nt = 0; nt < 4; nt++) {
                    uint32_t b0 = b[nt >> 1][(nt & 1) * 2];
                    uint32_t b1 = b[nt >> 1][(nt & 1) * 2 + 1];
                    asm volatile(
                        "mma.sync.aligned.m16n8k16.row.col.f32.bf16.bf16.f32 "
                        "{%0,%1,%2,%3}, {%4,%5,%6,%7}, {%8,%9}, {%0,%1,%2,%3};"
                        : "+f"(acc[mt][nt][0]), "+f"(acc[mt][nt][1]),
                          "+f"(acc[mt][nt][2]), "+f"(acc[mt][nt][3])
                        : "r"(a[mt][0]), "r"(a[mt][1]), "r"(a[mt][2]), "r"(a[mt][3]),
                          "r"(b0), "r"(b1));
                }
        }
    };

    load_stage(0, 0);
    asm volatile("cp.async.commit_group;");
    load_stage(1, 1);
    asm volatile("cp.async.commit_group;");

    #pragma unroll 1
    for (int kc = 0; kc < 8; kc++) {
        asm volatile("cp.async.wait_group 1;");
        __syncthreads();
        // prefetch kc+2 into stage (kc+2)%3 — safe: all threads finished
        // compute((kc+2)%3) == compute(kc-1) before the barrier above.
        if (kc + 2 < 8) {
            load_stage(kc + 2, (kc + 2) % 3);
            asm volatile("cp.async.commit_group;");
        } else {
            asm volatile("cp.async.commit_group;");   // keep group count in sync
        }
        compute(kc % 3);
    }

    // epilogue
    #pragma unroll
    for (int mt = 0; mt < 4; mt++)
        #pragma unroll
        for (int nt = 0; nt < 4; nt++) {
            int row = m0 + wm * 64 + mt * 16 + (lane >> 2);
            int col = n0 + wn * 32 + nt * 8 + (lane & 3) * 2;
            if (col < NN) {
                if (row < NN)
                    *(float2*)&C[(size_t)row * NN + col] =
                        make_float2(acc[mt][nt][0], acc[mt][nt][1]);
                if (row + 8 < NN)
                    *(float2*)&C[(size_t)(row + 8) * NN + col] =
                        make_float2(acc[mt][nt][2], acc[mt][nt][3]);
            }
        }
}

// ---------------- launcher ----------------
extern "C" void kernel_launch(void* const* d_in, const int* in_sizes, int n_in,
                              void* d_out, int out_size)
{
    const float* h   = (const float*)d_in[0];
    const float* W1a = (const float*)d_in[1];
    const float* b1a = (const float*)d_in[2];
    const float* W2a = (const float*)d_in[3];
    const float* b2a = (const float*)d_in[4];
    const float* W1s = (const float*)d_in[5];
    const float* b1s = (const float*)d_in[6];
    const float* W2s = (const float*)d_in[7];
    const float* b2s = (const float*)d_in[8];
    const int*   ei  = (const int*)d_in[9];
    const int* src = ei;
    const int* dst = ei + NE;
    float* out = (float*)d_out;

    float *pXW1, *pH1, *pXW2;
    __nv_bfloat16* pHb;
    cudaGetSymbolAddress((void**)&pXW1, g_XW1);
    cudaGetSymbolAddress((void**)&pH1,  g_H1);
    cudaGetSymbolAddress((void**)&pXW2, g_XW2);
    cudaGetSymbolAddress((void**)&pHb,  g_Hb);

    cudaFuncSetAttribute(gram_mma, cudaFuncAttributeMaxDynamicSharedMemorySize, GRAM_SMEM);

    // graph prep
    k_init <<<(NN + 255) / 256, 256>>>();
    k_count<<<(NE + 255) / 256, 256>>>(dst);
    k_scan <<<1, 1024>>>();
    k_dinv <<<(NN + 255) / 256, 256>>>();
    k_fill <<<(NE + 255) / 256, 256>>>(src, dst);

    const int MB = (NN + 127) / 128;   // 79

    // layer 1: XW1 = h @ [W1a | W1s]   (N, 512)
    sgemm<<<dim3(2, MB), 256>>>(h, IND, 0, W1a, 256, pXW1, F1, 0,   NN, 256, IND);
    sgemm<<<dim3(2, MB), 256>>>(h, IND, 0, W1s, 256, pXW1, F1, 256, NN, 256, IND);
    k_agg<<<NN, F1 / 4>>>((const float4*)pXW1, F1 / 4,
                          pH1, F1, pH1 + 256, F1, b1a, b1s, 256, 1);

    // layer 2
    sgemm<<<dim3(1, MB), 256>>>(pH1, F1, 0,   W2a, 128, pXW2, F2, 0,   NN, 128, 256);
    sgemm<<<dim3(1, MB), 256>>>(pH1, F1, 256, W2s, 128, pXW2, F2, 128, NN, 128, 256);
    k_agg2<<<NN, 64>>>((const float4*)pXW2, out, pHb, b2a, b2s);

    // s_ = h_ @ h_^T via bf16 tensor cores (split compensation, K=256)
    gram_mma<<<dim3(MB, MB), 256, GRAM_SMEM>>>(pHb, out + S_OFF);

    // h passthrough
    cudaMemcpyAsync(out + H_OFF, h, (size_t)NN * 128 * sizeof(float),
                    cudaMemcpyDeviceToDevice);
}

// round 6
// speedup vs baseline: 2.2079x; 1.1774x over previous
#include <cuda_runtime.h>
#include <cuda_bf16.h>
#include <cstdint>

// Problem constants
#define NN   10000
#define NE   320000
#define IND  128
#define F1   512     // 2*HID (combined a+s hidden)
#define F2   256     // 2*OUT

// Output layout: x_ [NN*128], s_ [NN*NN], h [NN*128]
#define S_OFF  (NN * 128)
#define H_OFF  (S_OFF + (size_t)NN * NN)

// ---------------- static device scratch (no allocs allowed) ----------------
__device__ float g_XW1[NN * F1];          // h @ [W1a | W1s]
__device__ float g_H1 [NN * F1];          // relu(agg(XW1) + b1)
__device__ float g_XW2[NN * F2];          // H1 @ [W2a | W2s]
__device__ __nv_bfloat16 g_Hb[NN * 256];  // h_ split: cols [0,128)=hi, [128,256)=lo
__device__ float g_dinv[NN];
__device__ int   g_cnt[NN];
__device__ int   g_cur[NN];
__device__ int   g_rowptr[NN + 1];
__device__ int   g_col[NE];

// ---------------- graph preprocessing ----------------
__global__ void k_init() {
    int i = blockIdx.x * 256 + threadIdx.x;
    if (i < NN) { g_cnt[i] = 0; g_cur[i] = 0; }
}

__global__ void k_count(const int* __restrict__ dst) {
    int e = blockIdx.x * 256 + threadIdx.x;
    if (e < NE) atomicAdd(&g_cnt[dst[e]], 1);
}

__global__ void k_scan() {
    __shared__ int s[1024];
    int t = threadIdx.x;
    const int CH = 10;
    int base = t * CH;
    int sum = 0;
    #pragma unroll
    for (int i = 0; i < CH; i++) { int idx = base + i; if (idx < NN) sum += g_cnt[idx]; }
    s[t] = sum;
    __syncthreads();
    for (int off = 1; off < 1024; off <<= 1) {
        int v = (t >= off) ? s[t - off] : 0;
        __syncthreads();
        s[t] += v;
        __syncthreads();
    }
    int run = (t > 0) ? s[t - 1] : 0;
    #pragma unroll
    for (int i = 0; i < CH; i++) {
        int idx = base + i;
        if (idx < NN) { g_rowptr[idx] = run; run += g_cnt[idx]; }
    }
    if (t == 1023) g_rowptr[NN] = s[1023];
}

__global__ void k_dinv() {
    int i = blockIdx.x * 256 + threadIdx.x;
    if (i < NN) g_dinv[i] = rsqrtf(1.0f + (float)g_cnt[i]);   // +1 self loop
}

__global__ void k_fill(const int* __restrict__ src, const int* __restrict__ dst) {
    int e = blockIdx.x * 256 + threadIdx.x;
    if (e < NE) {
        int d = dst[e];
        int pos = g_rowptr[d] + atomicAdd(&g_cur[d], 1);
        g_col[pos] = src[e];
    }
}

// ---------------- SGEMM (weights path): C[M,N] = A[M,K] * B[K,N] ----------------
__global__ void sgemm(const float* __restrict__ A, int lda, int aoff,
                      const float* __restrict__ B, int ldb,
                      float* __restrict__ C, int ldc, int coff,
                      int M, int N, int K)
{
    __shared__ float As[8][128];
    __shared__ float Bs[8][128];

    const int tid  = threadIdx.x;
    const int m0   = blockIdx.y * 128;
    const int n0   = blockIdx.x * 128;
    const int trow = tid >> 4;
    const int tcol = tid & 15;
    const int lrow = tid >> 1;
    const int lk4  = (tid & 1) * 4;
    const int brow = tid >> 5;
    const int bcol = (tid & 31) * 4;

    float acc[8][8];
    #pragma unroll
    for (int i = 0; i < 8; i++)
        #pragma unroll
        for (int j = 0; j < 8; j++) acc[i][j] = 0.0f;

    for (int k0 = 0; k0 < K; k0 += 8) {
        float4 av = make_float4(0.f, 0.f, 0.f, 0.f);
        if (m0 + lrow < M)
            av = *(const float4*)&A[(size_t)(m0 + lrow) * lda + aoff + k0 + lk4];
        As[lk4 + 0][lrow] = av.x; As[lk4 + 1][lrow] = av.y;
        As[lk4 + 2][lrow] = av.z; As[lk4 + 3][lrow] = av.w;

        float4 bv = *(const float4*)&B[(size_t)(k0 + brow) * ldb + n0 + bcol];
        *(float4*)&Bs[brow][bcol] = bv;
        __syncthreads();

        #pragma unroll
        for (int k = 0; k < 8; k++) {
            float a[8], b[8];
            *(float4*)&a[0] = *(const float4*)&As[k][trow * 4];
            *(float4*)&a[4] = *(const float4*)&As[k][64 + trow * 4];
            *(float4*)&b[0] = *(const float4*)&Bs[k][tcol * 4];
            *(float4*)&b[4] = *(const float4*)&Bs[k][64 + tcol * 4];
            #pragma unroll
            for (int i = 0; i < 8; i++)
                #pragma unroll
                for (int j = 0; j < 8; j++)
                    acc[i][j] += a[i] * b[j];
        }
        __syncthreads();
    }

    #pragma unroll
    for (int ih = 0; ih < 2; ih++)
        #pragma unroll
        for (int i = 0; i < 4; i++) {
            int row = m0 + ih * 64 + trow * 4 + i;
            if (row >= M) continue;
            #pragma unroll
            for (int jh = 0; jh < 2; jh++) {
                int col = n0 + jh * 64 + tcol * 4;
                float4 v = make_float4(acc[ih * 4 + i][jh * 4 + 0],
                                       acc[ih * 4 + i][jh * 4 + 1],
                                       acc[ih * 4 + i][jh * 4 + 2],
                                       acc[ih * 4 + i][jh * 4 + 3]);
                *(float4*)&C[(size_t)row * ldc + coff + col] = v;
            }
        }
}

// ---------------- GCN aggregation layer 1 (gather, no atomics) ----------------
__global__ void k_agg(const float4* __restrict__ XW4, int F4,
                      float* __restrict__ out_lo, int ld_lo,
                      float* __restrict__ out_hi, int ld_hi,
                      const float* __restrict__ ba, const float* __restrict__ bb,
                      int halfF, int do_relu)
{
    int n = blockIdx.x;
    int t = threadIdx.x;
    float di = g_dinv[n];
    float4 x = XW4[(size_t)n * F4 + t];
    float w0 = di * di;
    float4 acc = make_float4(x.x * w0, x.y * w0, x.z * w0, x.w * w0);

    int e0 = g_rowptr[n], e1 = g_rowptr[n + 1];
    for (int e = e0; e < e1; e++) {
        int s = g_col[e];
        float ws = g_dinv[s] * di;
        float4 v = XW4[(size_t)s * F4 + t];
        acc.x += v.x * ws; acc.y += v.y * ws;
        acc.z += v.z * ws; acc.w += v.w * ws;
    }

    int c = t * 4;
    if (c < halfF) {
        float4 bv = *(const float4*)&ba[c];
        acc.x += bv.x; acc.y += bv.y; acc.z += bv.z; acc.w += bv.w;
        if (do_relu) {
            acc.x = fmaxf(acc.x, 0.f); acc.y = fmaxf(acc.y, 0.f);
            acc.z = fmaxf(acc.z, 0.f); acc.w = fmaxf(acc.w, 0.f);
        }
        *(float4*)&out_lo[(size_t)n * ld_lo + c] = acc;
    } else {
        int cc = c - halfF;
        float4 bv = *(const float4*)&bb[cc];
        acc.x += bv.x; acc.y += bv.y; acc.z += bv.z; acc.w += bv.w;
        if (do_relu) {
            acc.x = fmaxf(acc.x, 0.f); acc.y = fmaxf(acc.y, 0.f);
            acc.z = fmaxf(acc.z, 0.f); acc.w = fmaxf(acc.w, 0.f);
        }
        *(float4*)&out_hi[(size_t)n * ld_hi + cc] = acc;
    }
}

// ---------------- GCN aggregation layer 2: x_ (fp32) + h_ (split bf16) ----------
struct alignas(8) bf4 { __nv_bfloat162 a, b; };

__global__ void k_agg2(const float4* __restrict__ XW4,   // [NN][64] float4 (F2=256)
                       float* __restrict__ xout,          // [NN][128]
                       __nv_bfloat16* __restrict__ Hb,    // [NN][256] hi|lo
                       const float* __restrict__ b2a, const float* __restrict__ b2s)
{
    int n = blockIdx.x;
    int t = threadIdx.x;   // 64 threads
    float di = g_dinv[n];
    float4 x = XW4[(size_t)n * 64 + t];
    float w0 = di * di;
    float4 acc = make_float4(x.x * w0, x.y * w0, x.z * w0, x.w * w0);

    int e0 = g_rowptr[n], e1 = g_rowptr[n + 1];
    for (int e = e0; e < e1; e++) {
        int s = g_col[e];
        float ws = g_dinv[s] * di;
        float4 v = XW4[(size_t)s * 64 + t];
        acc.x += v.x * ws; acc.y += v.y * ws;
        acc.z += v.z * ws; acc.w += v.w * ws;
    }

    int c = t * 4;
    if (c < 128) {
        float4 bv = *(const float4*)&b2a[c];
        acc.x += bv.x; acc.y += bv.y; acc.z += bv.z; acc.w += bv.w;
        *(float4*)&xout[(size_t)n * 128 + c] = acc;
    } else {
        int cc = c - 128;
        float4 bv = *(const float4*)&b2s[cc];
        acc.x += bv.x; acc.y += bv.y; acc.z += bv.z; acc.w += bv.w;
        __nv_bfloat16 h0 = __float2bfloat16(acc.x);
        __nv_bfloat16 h1 = __float2bfloat16(acc.y);
        __nv_bfloat16 h2 = __float2bfloat16(acc.z);
        __nv_bfloat16 h3 = __float2bfloat16(acc.w);
        __nv_bfloat16 l0 = __float2bfloat16(acc.x - __bfloat162float(h0));
        __nv_bfloat16 l1 = __float2bfloat16(acc.y - __bfloat162float(h1));
        __nv_bfloat16 l2 = __float2bfloat16(acc.z - __bfloat162float(h2));
        __nv_bfloat16 l3 = __float2bfloat16(acc.w - __bfloat162float(h3));
        bf4 hv; hv.a = __nv_bfloat162(h0, h1); hv.b = __nv_bfloat162(h2, h3);
        bf4 lv; lv.a = __nv_bfloat162(l0, l1); lv.b = __nv_bfloat162(l2, l3);
        *(bf4*)&Hb[(size_t)n * 256 + cc]       = hv;
        *(bf4*)&Hb[(size_t)n * 256 + 128 + cc] = lv;
    }
}

// ---------------- Gram via bf16 tensor cores (mma.sync), SYMMETRIC ----------------
// C[NN,NN] = Hb @ Hb^T over K=256 (split-bf16), fp32 accum.
// Only upper-triangular tiles (i<=j) computed; off-diagonal tiles written twice:
// direct from fragments + transposed via smem staging (pitch-66, coalesced).
#define BK 32
#define SP 40                       // smem row pitch in bf16 (80B)
#define STG_ELE (128 * SP)          // bf16 elements per tile stage
#define GRAM_SMEM (3 * 2 * STG_ELE * 2)   // 61440 bytes
#define NT 79                       // number of 128-bands
#define NTILES (NT * (NT + 1) / 2)  // 3160
#define TP 66                       // transpose staging pitch (floats)

__global__ void __launch_bounds__(256, 2)
gram_mma(const __nv_bfloat16* __restrict__ Hb, float* __restrict__ C)
{
    extern __shared__ __align__(16) __nv_bfloat16 smem[];
    __nv_bfloat16* As = smem;                 // [3][STG_ELE]
    __nv_bfloat16* Bs = smem + 3 * STG_ELE;   // [3][STG_ELE]
    float* sT = (float*)smem;                 // reused after mainloop: [128][TP]

    // ---- map linear tile id -> (ti, tj) with ti <= tj ----
    int t = blockIdx.x;
    int ti = (int)((2.0f * NT + 1.0f -
                    sqrtf((2.0f * NT + 1.0f) * (2.0f * NT + 1.0f) - 8.0f * (float)t)) * 0.5f);
    if (ti < 0) ti = 0;
    if (ti > NT - 1) ti = NT - 1;
    #pragma unroll 1
    while (ti > 0 && (ti * NT - ti * (ti - 1) / 2) > t) ti--;
    #pragma unroll 1
    while (ti < NT - 1 && ((ti + 1) * NT - (ti + 1) * ti / 2) <= t) ti++;
    const int tj = ti + (t - (ti * NT - ti * (ti - 1) / 2));

    const int m0 = ti * 128;
    const int n0 = tj * 128;

    const int tid  = threadIdx.x;
    const int w    = tid >> 5;
    const int lane = tid & 31;
    const int wm   = w >> 2;   // 0..1
    const int wn   = w & 3;    // 0..3

    float acc[4][4][4];
    #pragma unroll
    for (int mt = 0; mt < 4; mt++)
        #pragma unroll
        for (int nt = 0; nt < 4; nt++)
            #pragma unroll
            for (int i = 0; i < 4; i++) acc[mt][nt][i] = 0.0f;

    auto load_stage = [&](int kc, int st) {
        #pragma unroll
        for (int i = 0; i < 2; i++) {
            int c = tid + i * 256;            // 0..511
            int r = c >> 2, q = c & 3;        // row, 16B-chunk
            {
                int grow = m0 + r;
                int rg = grow < NN ? grow : NN - 1;
                const __nv_bfloat16* src = Hb + (size_t)rg * 256 + kc * BK + q * 8;
                uint32_t dst = (uint32_t)__cvta_generic_to_shared(&As[st * STG_ELE + r * SP + q * 8]);
                int sz = grow < NN ? 16 : 0;
                asm volatile("cp.async.cg.shared.global [%0], [%1], 16, %2;\n"
                             :: "r"(dst), "l"(src), "r"(sz));
            }
            {
                int grow = n0 + r;
                int rg = grow < NN ? grow : NN - 1;
                const __nv_bfloat16* src = Hb + (size_t)rg * 256 + kc * BK + q * 8;
                uint32_t dst = (uint32_t)__cvta_generic_to_shared(&Bs[st * STG_ELE + r * SP + q * 8]);
                int sz = grow < NN ? 16 : 0;
                asm volatile("cp.async.cg.shared.global [%0], [%1], 16, %2;\n"
                             :: "r"(dst), "l"(src), "r"(sz));
            }
        }
    };

    auto compute = [&](int st) {
        #pragma unroll
        for (int ks = 0; ks < 2; ks++) {
            uint32_t a[4][4];
            #pragma unroll
            for (int mt = 0; mt < 4; mt++) {
                int row = wm * 64 + mt * 16 + (lane & 15);
                int col = ks * 16 + ((lane >> 4) << 3);
                uint32_t ad = (uint32_t)__cvta_generic_to_shared(&As[st * STG_ELE + row * SP + col]);
                asm volatile("ldmatrix.sync.aligned.m8n8.x4.shared.b16 {%0,%1,%2,%3}, [%4];"
                             : "=r"(a[mt][0]), "=r"(a[mt][1]), "=r"(a[mt][2]), "=r"(a[mt][3])
                             : "r"(ad));
            }
            uint32_t b[2][4];
            #pragma unroll
            for (int p = 0; p < 2; p++) {
                int j = lane >> 3, l = lane & 7;
                int row = wn * 32 + p * 16 + ((j >> 1) << 3) + l;
                int col = ks * 16 + ((j & 1) << 3);
                uint32_t bd = (uint32_t)__cvta_generic_to_shared(&Bs[st * STG_ELE + row * SP + col]);
                asm volatile("ldmatrix.sync.aligned.m8n8.x4.shared.b16 {%0,%1,%2,%3}, [%4];"
                             : "=r"(b[p][0]), "=r"(b[p][1]), "=r"(b[p][2]), "=r"(b[p][3])
                             : "r"(bd));
            }
            #pragma unroll
            for (int mt = 0; mt < 4; mt++)
                #pragma unroll
                for (int nt = 0; nt < 4; nt++) {
                    uint32_t b0 = b[nt >> 1][(nt & 1) * 2];
                    uint32_t b1 = b[nt >> 1][(nt & 1) * 2 + 1];
                    asm volatile(
                        "mma.sync.aligned.m16n8k16.row.col.f32.bf16.bf16.f32 "
                        "{%0,%1,%2,%3}, {%4,%5,%6,%7}, {%8,%9}, {%0,%1,%2,%3};"
                        : "+f"(acc[mt][nt][0]), "+f"(acc[mt][nt][1]),
                          "+f"(acc[mt][nt][2]), "+f"(acc[mt][nt][3])
                        : "r"(a[mt][0]), "r"(a[mt][1]), "r"(a[mt][2]), "r"(a[mt][3]),
                          "r"(b0), "r"(b1));
                }
        }
    };

    load_stage(0, 0);
    asm volatile("cp.async.commit_group;");
    load_stage(1, 1);
    asm volatile("cp.async.commit_group;");

    #pragma unroll 1
    for (int kc = 0; kc < 8; kc++) {
        asm volatile("cp.async.wait_group 1;");
        __syncthreads();
        if (kc + 2 < 8) {
            load_stage(kc + 2, (kc + 2) % 3);
            asm volatile("cp.async.commit_group;");
        } else {
            asm volatile("cp.async.commit_group;");   // keep group count in sync
        }
        compute(kc % 3);
    }

    // ---- direct write: C[m0 + rows, n0 + cols] ----
    #pragma unroll
    for (int mt = 0; mt < 4; mt++)
        #pragma unroll
        for (int nt = 0; nt < 4; nt++) {
            int row = m0 + wm * 64 + mt * 16 + (lane >> 2);
            int col = n0 + wn * 32 + nt * 8 + (lane & 3) * 2;
            if (col < NN) {
                if (row < NN)
                    *(float2*)&C[(size_t)row * NN + col] =
                        make_float2(acc[mt][nt][0], acc[mt][nt][1]);
                if (row + 8 < NN)
                    *(float2*)&C[(size_t)(row + 8) * NN + col] =
                        make_float2(acc[mt][nt][2], acc[mt][nt][3]);
            }
        }

    // ---- transposed write for off-diagonal tiles: C[n0 + cc, m0 + rr] ----
    if (ti != tj) {
        #pragma unroll
        for (int h = 0; h < 2; h++) {
            __syncthreads();   // smem (pipeline buffers) free / prev phase done
            if (wm == h) {
                // stage this half's fragments transposed: sT[cloc][rloc], rloc in 0..63
                #pragma unroll
                for (int mt = 0; mt < 4; mt++) {
                    int rloc = mt * 16 + (lane >> 2);   // 0..63 within half
                    #pragma unroll
                    for (int nt = 0; nt < 4; nt++) {
                        int cloc = wn * 32 + nt * 8 + (lane & 3) * 2;
                        sT[(cloc)     * TP + rloc]     = acc[mt][nt][0];
                        sT[(cloc + 1) * TP + rloc]     = acc[mt][nt][1];
                        sT[(cloc)     * TP + rloc + 8] = acc[mt][nt][2];
                        sT[(cloc + 1) * TP + rloc + 8] = acc[mt][nt][3];
                    }
                }
            }
            __syncthreads();
            // emit: 128 output rows (cc) x 64 cols (rr) = 2048 float4
            #pragma unroll
            for (int e = 0; e < 8; e++) {
                int idx = tid + 256 * e;       // 0..2047
                int cc  = idx >> 4;            // 0..127
                int rr  = (idx & 15) * 4;      // 0..60
                int grow = n0 + cc;
                int gcol = m0 + h * 64 + rr;
                if (grow < NN) {
                    float4 v = make_float4(sT[cc * TP + rr],
                                           sT[cc * TP + rr + 1],
                                           sT[cc * TP + rr + 2],
                                           sT[cc * TP + rr + 3]);
                    if (gcol + 3 < NN) {
                        *(float4*)&C[(size_t)grow * NN + gcol] = v;
                    } else {
                        float vv[4] = {v.x, v.y, v.z, v.w};
                        #pragma unroll
                        for (int k = 0; k < 4; k++)
                            if (gcol + k < NN) C[(size_t)grow * NN + gcol + k] = vv[k];
                    }
                }
            }
        }
    }
}

// ---------------- launcher ----------------
extern "C" void kernel_launch(void* const* d_in, const int* in_sizes, int n_in,
                              void* d_out, int out_size)
{
    const float* h   = (const float*)d_in[0];
    const float* W1a = (const float*)d_in[1];
    const float* b1a = (const float*)d_in[2];
    const float* W2a = (const float*)d_in[3];
    const float* b2a = (const float*)d_in[4];
    const float* W1s = (const float*)d_in[5];
    const float* b1s = (const float*)d_in[6];
    const float* W2s = (const float*)d_in[7];
    const float* b2s = (const float*)d_in[8];
    const int*   ei  = (const int*)d_in[9];
    const int* src = ei;
    const int* dst = ei + NE;
    float* out = (float*)d_out;

    float *pXW1, *pH1, *pXW2;
    __nv_bfloat16* pHb;
    cudaGetSymbolAddress((void**)&pXW1, g_XW1);
    cudaGetSymbolAddress((void**)&pH1,  g_H1);
    cudaGetSymbolAddress((void**)&pXW2, g_XW2);
    cudaGetSymbolAddress((void**)&pHb,  g_Hb);

    cudaFuncSetAttribute(gram_mma, cudaFuncAttributeMaxDynamicSharedMemorySize, GRAM_SMEM);

    // graph prep
    k_init <<<(NN + 255) / 256, 256>>>();
    k_count<<<(NE + 255) / 256, 256>>>(dst);
    k_scan <<<1, 1024>>>();
    k_dinv <<<(NN + 255) / 256, 256>>>();
    k_fill <<<(NE + 255) / 256, 256>>>(src, dst);

    const int MB = (NN + 127) / 128;   // 79

    // layer 1: XW1 = h @ [W1a | W1s]   (N, 512)
    sgemm<<<dim3(2, MB), 256>>>(h, IND, 0, W1a, 256, pXW1, F1, 0,   NN, 256, IND);
    sgemm<<<dim3(2, MB), 256>>>(h, IND, 0, W1s, 256, pXW1, F1, 256, NN, 256, IND);
    k_agg<<<NN, F1 / 4>>>((const float4*)pXW1, F1 / 4,
                          pH1, F1, pH1 + 256, F1, b1a, b1s, 256, 1);

    // layer 2
    sgemm<<<dim3(1, MB), 256>>>(pH1, F1, 0,   W2a, 128, pXW2, F2, 0,   NN, 128, 256);
    sgemm<<<dim3(1, MB), 256>>>(pH1, F1, 256, W2s, 128, pXW2, F2, 128, NN, 128, 256);
    k_agg2<<<NN, 64>>>((const float4*)pXW2, out, pHb, b2a, b2s);

    // s_ = h_ @ h_^T via bf16 tensor cores, symmetric (upper tiles only)
    gram_mma<<<NTILES, 256, GRAM_SMEM>>>(pHb, out + S_OFF);

    // h passthrough
    cudaMemcpyAsync(out + H_OFF, h, (size_t)NN * 128 * sizeof(float),
                    cudaMemcpyDeviceToDevice);
}

// round 7
// speedup vs baseline: 2.8383x; 1.2855x over previous
#include <cuda_runtime.h>
#include <cuda_bf16.h>
#include <cstdint>

// Problem constants
#define NN   10000
#define NE   320000
#define IND  128
#define F1   512     // 2*HID (combined a+s hidden)
#define F2   256     // 2*OUT

// Output layout: x_ [NN*128], s_ [NN*NN], h [NN*128]
#define S_OFF  (NN * 128)
#define H_OFF  (S_OFF + (size_t)NN * NN)

// ---------------- static device scratch (no allocs allowed) ----------------
__device__ float g_XW1[NN * F1];              // h @ [W1a | W1s]  (fp32, gathered by agg1)
__device__ float g_XW2[NN * F2];              // H1 @ [W2a | W2s] (fp32, gathered by agg2)
__device__ __nv_bfloat16 g_A1 [NN * 384];     // h split:  [hi | lo | hi]        (K=384)
__device__ __nv_bfloat16 g_A2a[NN * 768];     // H1a split: [hi | lo | hi]       (K=768)
__device__ __nv_bfloat16 g_A2s[NN * 768];     // H1s split
__device__ __nv_bfloat16 g_WT1 [512 * 384];   // [W1a|W1s]^T split: [whi | whi | wlo]
__device__ __nv_bfloat16 g_WT2a[128 * 768];   // W2a^T split
__device__ __nv_bfloat16 g_WT2s[128 * 768];   // W2s^T split
__device__ __nv_bfloat16 g_Hb[NN * 256];      // h_ split: cols [0,128)=hi, [128,256)=lo
__device__ float g_dinv[NN];
__device__ int   g_cnt[NN];
__device__ int   g_cur[NN];
__device__ int   g_rowptr[NN + 1];
__device__ int   g_col[NE];

// ---------------- graph preprocessing ----------------
__global__ void k_init() {
    int i = blockIdx.x * 256 + threadIdx.x;
    if (i < NN) { g_cnt[i] = 0; g_cur[i] = 0; }
}

__global__ void k_count(const int* __restrict__ dst) {
    int e = blockIdx.x * 256 + threadIdx.x;
    if (e < NE) atomicAdd(&g_cnt[dst[e]], 1);
}

__global__ void k_scan() {
    __shared__ int s[1024];
    int t = threadIdx.x;
    const int CH = 10;
    int base = t * CH;
    int sum = 0;
    #pragma unroll
    for (int i = 0; i < CH; i++) { int idx = base + i; if (idx < NN) sum += g_cnt[idx]; }
    s[t] = sum;
    __syncthreads();
    for (int off = 1; off < 1024; off <<= 1) {
        int v = (t >= off) ? s[t - off] : 0;
        __syncthreads();
        s[t] += v;
        __syncthreads();
    }
    int run = (t > 0) ? s[t - 1] : 0;
    #pragma unroll
    for (int i = 0; i < CH; i++) {
        int idx = base + i;
        if (idx < NN) { g_rowptr[idx] = run; run += g_cnt[idx]; }
    }
    if (t == 1023) g_rowptr[NN] = s[1023];
}

__global__ void k_dinv() {
    int i = blockIdx.x * 256 + threadIdx.x;
    if (i < NN) g_dinv[i] = rsqrtf(1.0f + (float)g_cnt[i]);   // +1 self loop
}

__global__ void k_fill(const int* __restrict__ src, const int* __restrict__ dst) {
    int e = blockIdx.x * 256 + threadIdx.x;
    if (e < NE) {
        int d = dst[e];
        int pos = g_rowptr[d] + atomicAdd(&g_cur[d], 1);
        g_col[pos] = src[e];
    }
}

// ---------------- split conversions ----------------
struct alignas(8) bf4 { __nv_bfloat162 a, b; };

__device__ __forceinline__ void split4(float4 v, bf4& hv, bf4& lv) {
    __nv_bfloat16 h0 = __float2bfloat16(v.x), h1 = __float2bfloat16(v.y);
    __nv_bfloat16 h2 = __float2bfloat16(v.z), h3 = __float2bfloat16(v.w);
    __nv_bfloat16 l0 = __float2bfloat16(v.x - __bfloat162float(h0));
    __nv_bfloat16 l1 = __float2bfloat16(v.y - __bfloat162float(h1));
    __nv_bfloat16 l2 = __float2bfloat16(v.z - __bfloat162float(h2));
    __nv_bfloat16 l3 = __float2bfloat16(v.w - __bfloat162float(h3));
    hv.a = __nv_bfloat162(h0, h1); hv.b = __nv_bfloat162(h2, h3);
    lv.a = __nv_bfloat162(l0, l1); lv.b = __nv_bfloat162(l2, l3);
}

// h [NN,128] fp32 -> g_A1 [NN, 384]: [hi | lo | hi]
__global__ void k_split_h(const float4* __restrict__ h4) {
    int n = blockIdx.x, t = threadIdx.x;   // 32 threads
    float4 v = h4[(size_t)n * 32 + t];
    bf4 hv, lv; split4(v, hv, lv);
    int c = t * 4;
    *(bf4*)&g_A1[(size_t)n * 384 + c]       = hv;
    *(bf4*)&g_A1[(size_t)n * 384 + 128 + c] = lv;
    *(bf4*)&g_A1[(size_t)n * 384 + 256 + c] = hv;
}

// W1a/W1s [128,256] -> g_WT1 [512, 384]: row n = output feature, [whi | whi | wlo]
__global__ void k_split_w1(const float* __restrict__ W1a, const float* __restrict__ W1s) {
    int n = blockIdx.x;    // 0..511
    int k = threadIdx.x;   // 0..127
    const float* W = (n < 256) ? W1a : W1s;
    int col = n & 255;
    float v = W[k * 256 + col];
    __nv_bfloat16 hi = __float2bfloat16(v);
    __nv_bfloat16 lo = __float2bfloat16(v - __bfloat162float(hi));
    g_WT1[(size_t)n * 384 + k]       = hi;
    g_WT1[(size_t)n * 384 + 128 + k] = hi;
    g_WT1[(size_t)n * 384 + 256 + k] = lo;
}

// W2a/W2s [256,128] -> g_WT2{a,s} [128, 768]
__global__ void k_split_w2(const float* __restrict__ W2a, const float* __restrict__ W2s) {
    int n = blockIdx.x;    // 0..127 output feature
    int k = threadIdx.x;   // 0..255
    const float* W = blockIdx.y ? W2s : W2a;
    __nv_bfloat16* dst = blockIdx.y ? g_WT2s : g_WT2a;
    float v = W[k * 128 + n];
    __nv_bfloat16 hi = __float2bfloat16(v);
    __nv_bfloat16 lo = __float2bfloat16(v - __bfloat162float(hi));
    dst[(size_t)n * 768 + k]       = hi;
    dst[(size_t)n * 768 + 256 + k] = hi;
    dst[(size_t)n * 768 + 512 + k] = lo;
}

// ---------------- GCN aggregation layer 1: H1 = relu(agg(XW1)+b), split to A2 ----
__global__ void k_agg1(const float4* __restrict__ XW4,   // [NN][128] float4 (F1=512)
                       const float* __restrict__ b1a, const float* __restrict__ b1s)
{
    int n = blockIdx.x;
    int t = threadIdx.x;   // 128 threads
    float di = g_dinv[n];
    float4 x = XW4[(size_t)n * 128 + t];
    float w0 = di * di;
    float4 acc = make_float4(x.x * w0, x.y * w0, x.z * w0, x.w * w0);

    int e0 = g_rowptr[n], e1 = g_rowptr[n + 1];
    for (int e = e0; e < e1; e++) {
        int s = g_col[e];
        float ws = g_dinv[s] * di;
        float4 v = XW4[(size_t)s * 128 + t];
        acc.x += v.x * ws; acc.y += v.y * ws;
        acc.z += v.z * ws; acc.w += v.w * ws;
    }

    int c = t * 4;
    __nv_bfloat16* dst;
    int lc;
    const float* bias;
    if (c < 256) { dst = g_A2a; lc = c;       bias = b1a + lc; }
    else         { dst = g_A2s; lc = c - 256; bias = b1s + lc; }
    float4 bv = *(const float4*)bias;
    acc.x = fmaxf(acc.x + bv.x, 0.f); acc.y = fmaxf(acc.y + bv.y, 0.f);
    acc.z = fmaxf(acc.z + bv.z, 0.f); acc.w = fmaxf(acc.w + bv.w, 0.f);
    bf4 hv, lv; split4(acc, hv, lv);
    *(bf4*)&dst[(size_t)n * 768 + lc]       = hv;
    *(bf4*)&dst[(size_t)n * 768 + 256 + lc] = lv;
    *(bf4*)&dst[(size_t)n * 768 + 512 + lc] = hv;
}

// ---------------- GCN aggregation layer 2: x_ (fp32) + h_ (split bf16) ----------
__global__ void k_agg2(const float4* __restrict__ XW4,   // [NN][64] float4 (F2=256)
                       float* __restrict__ xout,          // [NN][128]
                       __nv_bfloat16* __restrict__ Hb,    // [NN][256] hi|lo
                       const float* __restrict__ b2a, const float* __restrict__ b2s)
{
    int n = blockIdx.x;
    int t = threadIdx.x;   // 64 threads
    float di = g_dinv[n];
    float4 x = XW4[(size_t)n * 64 + t];
    float w0 = di * di;
    float4 acc = make_float4(x.x * w0, x.y * w0, x.z * w0, x.w * w0);

    int e0 = g_rowptr[n], e1 = g_rowptr[n + 1];
    for (int e = e0; e < e1; e++) {
        int s = g_col[e];
        float ws = g_dinv[s] * di;
        float4 v = XW4[(size_t)s * 64 + t];
        acc.x += v.x * ws; acc.y += v.y * ws;
        acc.z += v.z * ws; acc.w += v.w * ws;
    }

    int c = t * 4;
    if (c < 128) {
        float4 bv = *(const float4*)&b2a[c];
        acc.x += bv.x; acc.y += bv.y; acc.z += bv.z; acc.w += bv.w;
        *(float4*)&xout[(size_t)n * 128 + c] = acc;
    } else {
        int cc = c - 128;
        float4 bv = *(const float4*)&b2s[cc];
        acc.x += bv.x; acc.y += bv.y; acc.z += bv.z; acc.w += bv.w;
        bf4 hv, lv; split4(acc, hv, lv);
        *(bf4*)&Hb[(size_t)n * 256 + cc]       = hv;
        *(bf4*)&Hb[(size_t)n * 256 + 128 + cc] = lv;
    }
}

// ---------------- bf16 tensor-core GEMM: C[M,N] = A[M,K] @ B[N,K]^T ----------------
// A, B row-major bf16 (B rows = output features). fp32 out. N tiles full (N%128==0).
#define BK 32
#define SP 40                       // smem row pitch in bf16 (80B)
#define STG_ELE (128 * SP)
#define GRAM_SMEM (3 * 2 * STG_ELE * 2)   // 61440 bytes

__global__ void __launch_bounds__(256, 2)
gemm_bf(const __nv_bfloat16* __restrict__ A, const __nv_bfloat16* __restrict__ B,
        int K, float* __restrict__ C, int ldc, int coff, int M)
{
    extern __shared__ __align__(16) __nv_bfloat16 smem[];
    __nv_bfloat16* As = smem;
    __nv_bfloat16* Bs = smem + 3 * STG_ELE;

    const int tid  = threadIdx.x;
    const int m0   = blockIdx.y * 128;
    const int n0   = blockIdx.x * 128;
    const int w    = tid >> 5;
    const int lane = tid & 31;
    const int wm   = w >> 2;
    const int wn   = w & 3;
    const int nch  = K / BK;

    float acc[4][4][4];
    #pragma unroll
    for (int mt = 0; mt < 4; mt++)
        #pragma unroll
        for (int nt = 0; nt < 4; nt++)
            #pragma unroll
            for (int i = 0; i < 4; i++) acc[mt][nt][i] = 0.0f;

    auto load_stage = [&](int kc, int st) {
        #pragma unroll
        for (int i = 0; i < 2; i++) {
            int c = tid + i * 256;
            int r = c >> 2, q = c & 3;
            {
                int grow = m0 + r;
                int rg = grow < M ? grow : M - 1;
                const __nv_bfloat16* src = A + (size_t)rg * K + kc * BK + q * 8;
                uint32_t dst = (uint32_t)__cvta_generic_to_shared(&As[st * STG_ELE + r * SP + q * 8]);
                asm volatile("cp.async.cg.shared.global [%0], [%1], 16;\n"
                             :: "r"(dst), "l"(src));
            }
            {
                const __nv_bfloat16* src = B + (size_t)(n0 + r) * K + kc * BK + q * 8;
                uint32_t dst = (uint32_t)__cvta_generic_to_shared(&Bs[st * STG_ELE + r * SP + q * 8]);
                asm volatile("cp.async.cg.shared.global [%0], [%1], 16;\n"
                             :: "r"(dst), "l"(src));
            }
        }
    };

    auto compute = [&](int st) {
        #pragma unroll
        for (int ks = 0; ks < 2; ks++) {
            uint32_t a[4][4];
            #pragma unroll
            for (int mt = 0; mt < 4; mt++) {
                int row = wm * 64 + mt * 16 + (lane & 15);
                int col = ks * 16 + ((lane >> 4) << 3);
                uint32_t ad = (uint32_t)__cvta_generic_to_shared(&As[st * STG_ELE + row * SP + col]);
                asm volatile("ldmatrix.sync.aligned.m8n8.x4.shared.b16 {%0,%1,%2,%3}, [%4];"
                             : "=r"(a[mt][0]), "=r"(a[mt][1]), "=r"(a[mt][2]), "=r"(a[mt][3])
                             : "r"(ad));
            }
            uint32_t b[2][4];
            #pragma unroll
            for (int p = 0; p < 2; p++) {
                int j = lane >> 3, l = lane & 7;
                int row = wn * 32 + p * 16 + ((j >> 1) << 3) + l;
                int col = ks * 16 + ((j & 1) << 3);
                uint32_t bd = (uint32_t)__cvta_generic_to_shared(&Bs[st * STG_ELE + row * SP + col]);
                asm volatile("ldmatrix.sync.aligned.m8n8.x4.shared.b16 {%0,%1,%2,%3}, [%4];"
                             : "=r"(b[p][0]), "=r"(b[p][1]), "=r"(b[p][2]), "=r"(b[p][3])
                             : "r"(bd));
            }
            #pragma unroll
            for (int mt = 0; mt < 4; mt++)
                #pragma unroll
                for (int nt = 0; nt < 4; nt++) {
                    uint32_t b0 = b[nt >> 1][(nt & 1) * 2];
                    uint32_t b1 = b[nt >> 1][(nt & 1) * 2 + 1];
                    asm volatile(
                        "mma.sync.aligned.m16n8k16.row.col.f32.bf16.bf16.f32 "
                        "{%0,%1,%2,%3}, {%4,%5,%6,%7}, {%8,%9}, {%0,%1,%2,%3};"
                        : "+f"(acc[mt][nt][0]), "+f"(acc[mt][nt][1]),
                          "+f"(acc[mt][nt][2]), "+f"(acc[mt][nt][3])
                        : "r"(a[mt][0]), "r"(a[mt][1]), "r"(a[mt][2]), "r"(a[mt][3]),
                          "r"(b0), "r"(b1));
                }
        }
    };

    load_stage(0, 0);
    asm volatile("cp.async.commit_group;");
    load_stage(1, 1);
    asm volatile("cp.async.commit_group;");

    #pragma unroll 1
    for (int kc = 0; kc < nch; kc++) {
        asm volatile("cp.async.wait_group 1;");
        __syncthreads();
        if (kc + 2 < nch) {
            load_stage(kc + 2, (kc + 2) % 3);
            asm volatile("cp.async.commit_group;");
        } else {
            asm volatile("cp.async.commit_group;");
        }
        compute(kc % 3);
    }

    #pragma unroll
    for (int mt = 0; mt < 4; mt++)
        #pragma unroll
        for (int nt = 0; nt < 4; nt++) {
            int row = m0 + wm * 64 + mt * 16 + (lane >> 2);
            int col = n0 + wn * 32 + nt * 8 + (lane & 3) * 2;
            if (row < M)
                *(float2*)&C[(size_t)row * ldc + coff + col] =
                    make_float2(acc[mt][nt][0], acc[mt][nt][1]);
            if (row + 8 < M)
                *(float2*)&C[(size_t)(row + 8) * ldc + coff + col] =
                    make_float2(acc[mt][nt][2], acc[mt][nt][3]);
        }
}

// ---------------- Gram via bf16 tensor cores (mma.sync), SYMMETRIC ----------------
#define NT 79
#define NTILES (NT * (NT + 1) / 2)  // 3160
#define TP 66                       // transpose staging pitch (floats)

__global__ void __launch_bounds__(256, 2)
gram_mma(const __nv_bfloat16* __restrict__ Hb, float* __restrict__ C)
{
    extern __shared__ __align__(16) __nv_bfloat16 smem[];
    __nv_bfloat16* As = smem;
    __nv_bfloat16* Bs = smem + 3 * STG_ELE;
    float* sT = (float*)smem;

    int t = blockIdx.x;
    int ti = (int)((2.0f * NT + 1.0f -
                    sqrtf((2.0f * NT + 1.0f) * (2.0f * NT + 1.0f) - 8.0f * (float)t)) * 0.5f);
    if (ti < 0) ti = 0;
    if (ti > NT - 1) ti = NT - 1;
    #pragma unroll 1
    while (ti > 0 && (ti * NT - ti * (ti - 1) / 2) > t) ti--;
    #pragma unroll 1
    while (ti < NT - 1 && ((ti + 1) * NT - (ti + 1) * ti / 2) <= t) ti++;
    const int tj = ti + (t - (ti * NT - ti * (ti - 1) / 2));

    const int m0 = ti * 128;
    const int n0 = tj * 128;

    const int tid  = threadIdx.x;
    const int w    = tid >> 5;
    const int lane = tid & 31;
    const int wm   = w >> 2;
    const int wn   = w & 3;

    float acc[4][4][4];
    #pragma unroll
    for (int mt = 0; mt < 4; mt++)
        #pragma unroll
        for (int nt = 0; nt < 4; nt++)
            #pragma unroll
            for (int i = 0; i < 4; i++) acc[mt][nt][i] = 0.0f;

    auto load_stage = [&](int kc, int st) {
        #pragma unroll
        for (int i = 0; i < 2; i++) {
            int c = tid + i * 256;
            int r = c >> 2, q = c & 3;
            {
                int grow = m0 + r;
                int rg = grow < NN ? grow : NN - 1;
                const __nv_bfloat16* src = Hb + (size_t)rg * 256 + kc * BK + q * 8;
                uint32_t dst = (uint32_t)__cvta_generic_to_shared(&As[st * STG_ELE + r * SP + q * 8]);
                asm volatile("cp.async.cg.shared.global [%0], [%1], 16;\n"
                             :: "r"(dst), "l"(src));
            }
            {
                int grow = n0 + r;
                int rg = grow < NN ? grow : NN - 1;
                const __nv_bfloat16* src = Hb + (size_t)rg * 256 + kc * BK + q * 8;
                uint32_t dst = (uint32_t)__cvta_generic_to_shared(&Bs[st * STG_ELE + r * SP + q * 8]);
                asm volatile("cp.async.cg.shared.global [%0], [%1], 16;\n"
                             :: "r"(dst), "l"(src));
            }
        }
    };

    auto compute = [&](int st) {
        #pragma unroll
        for (int ks = 0; ks < 2; ks++) {
            uint32_t a[4][4];
            #pragma unroll
            for (int mt = 0; mt < 4; mt++) {
                int row = wm * 64 + mt * 16 + (lane & 15);
                int col = ks * 16 + ((lane >> 4) << 3);
                uint32_t ad = (uint32_t)__cvta_generic_to_shared(&As[st * STG_ELE + row * SP + col]);
                asm volatile("ldmatrix.sync.aligned.m8n8.x4.shared.b16 {%0,%1,%2,%3}, [%4];"
                             : "=r"(a[mt][0]), "=r"(a[mt][1]), "=r"(a[mt][2]), "=r"(a[mt][3])
                             : "r"(ad));
            }
            uint32_t b[2][4];
            #pragma unroll
            for (int p = 0; p < 2; p++) {
                int j = lane >> 3, l = lane & 7;
                int row = wn * 32 + p * 16 + ((j >> 1) << 3) + l;
                int col = ks * 16 + ((j & 1) << 3);
                uint32_t bd = (uint32_t)__cvta_generic_to_shared(&Bs[st * STG_ELE + row * SP + col]);
                asm volatile("ldmatrix.sync.aligned.m8n8.x4.shared.b16 {%0,%1,%2,%3}, [%4];"
                             : "=r"(b[p][0]), "=r"(b[p][1]), "=r"(b[p][2]), "=r"(b[p][3])
                             : "r"(bd));
            }
            #pragma unroll
            for (int mt = 0; mt < 4; mt++)
                #pragma unroll
                for (int nt = 0; nt < 4; nt++) {
                    uint32_t b0 = b[nt >> 1][(nt & 1) * 2];
                    uint32_t b1 = b[nt >> 1][(nt & 1) * 2 + 1];
                    asm volatile(
                        "mma.sync.aligned.m16n8k16.row.col.f32.bf16.bf16.f32 "
                        "{%0,%1,%2,%3}, {%4,%5,%6,%7}, {%8,%9}, {%0,%1,%2,%3};"
                        : "+f"(acc[mt][nt][0]), "+f"(acc[mt][nt][1]),
                          "+f"(acc[mt][nt][2]), "+f"(acc[mt][nt][3])
                        : "r"(a[mt][0]), "r"(a[mt][1]), "r"(a[mt][2]), "r"(a[mt][3]),
                          "r"(b0), "r"(b1));
                }
        }
    };

    load_stage(0, 0);
    asm volatile("cp.async.commit_group;");
    load_stage(1, 1);
    asm volatile("cp.async.commit_group;");

    #pragma unroll 1
    for (int kc = 0; kc < 8; kc++) {
        asm volatile("cp.async.wait_group 1;");
        __syncthreads();
        if (kc + 2 < 8) {
            load_stage(kc + 2, (kc + 2) % 3);
            asm volatile("cp.async.commit_group;");
        } else {
            asm volatile("cp.async.commit_group;");
        }
        compute(kc % 3);
    }

    #pragma unroll
    for (int mt = 0; mt < 4; mt++)
        #pragma unroll
        for (int nt = 0; nt < 4; nt++) {
            int row = m0 + wm * 64 + mt * 16 + (lane >> 2);
            int col = n0 + wn * 32 + nt * 8 + (lane & 3) * 2;
            if (col < NN) {
                if (row < NN)
                    *(float2*)&C[(size_t)row * NN + col] =
                        make_float2(acc[mt][nt][0], acc[mt][nt][1]);
                if (row + 8 < NN)
                    *(float2*)&C[(size_t)(row + 8) * NN + col] =
                        make_float2(acc[mt][nt][2], acc[mt][nt][3]);
            }
        }

    if (ti != tj) {
        #pragma unroll
        for (int h = 0; h < 2; h++) {
            __syncthreads();
            if (wm == h) {
                #pragma unroll
                for (int mt = 0; mt < 4; mt++) {
                    int rloc = mt * 16 + (lane >> 2);
                    #pragma unroll
                    for (int nt = 0; nt < 4; nt++) {
                        int cloc = wn * 32 + nt * 8 + (lane & 3) * 2;
                        sT[(cloc)     * TP + rloc]     = acc[mt][nt][0];
                        sT[(cloc + 1) * TP + rloc]     = acc[mt][nt][1];
                        sT[(cloc)     * TP + rloc + 8] = acc[mt][nt][2];
                        sT[(cloc + 1) * TP + rloc + 8] = acc[mt][nt][3];
                    }
                }
            }
            __syncthreads();
            #pragma unroll
            for (int e = 0; e < 8; e++) {
                int idx = tid + 256 * e;
                int cc  = idx >> 4;
                int rr  = (idx & 15) * 4;
                int grow = n0 + cc;
                int gcol = m0 + h * 64 + rr;
                if (grow < NN) {
                    float4 v = make_float4(sT[cc * TP + rr],
                                           sT[cc * TP + rr + 1],
                                           sT[cc * TP + rr + 2],
                                           sT[cc * TP + rr + 3]);
                    if (gcol + 3 < NN) {
                        *(float4*)&C[(size_t)grow * NN + gcol] = v;
                    } else {
                        float vv[4] = {v.x, v.y, v.z, v.w};
                        #pragma unroll
                        for (int k = 0; k < 4; k++)
                            if (gcol + k < NN) C[(size_t)grow * NN + gcol + k] = vv[k];
                    }
                }
            }
        }
    }
}

// ---------------- launcher ----------------
extern "C" void kernel_launch(void* const* d_in, const int* in_sizes, int n_in,
                              void* d_out, int out_size)
{
    const float* h   = (const float*)d_in[0];
    const float* W1a = (const float*)d_in[1];
    const float* b1a = (const float*)d_in[2];
    const float* W2a = (const float*)d_in[3];
    const float* b2a = (const float*)d_in[4];
    const float* W1s = (const float*)d_in[5];
    const float* b1s = (const float*)d_in[6];
    const float* W2s = (const float*)d_in[7];
    const float* b2s = (const float*)d_in[8];
    const int*   ei  = (const int*)d_in[9];
    const int* src = ei;
    const int* dst = ei + NE;
    float* out = (float*)d_out;

    float *pXW1, *pXW2;
    __nv_bfloat16 *pHb, *pA1, *pA2a, *pA2s, *pWT1, *pWT2a, *pWT2s;
    cudaGetSymbolAddress((void**)&pXW1,  g_XW1);
    cudaGetSymbolAddress((void**)&pXW2,  g_XW2);
    cudaGetSymbolAddress((void**)&pHb,   g_Hb);
    cudaGetSymbolAddress((void**)&pA1,   g_A1);
    cudaGetSymbolAddress((void**)&pA2a,  g_A2a);
    cudaGetSymbolAddress((void**)&pA2s,  g_A2s);
    cudaGetSymbolAddress((void**)&pWT1,  g_WT1);
    cudaGetSymbolAddress((void**)&pWT2a, g_WT2a);
    cudaGetSymbolAddress((void**)&pWT2s, g_WT2s);

    cudaFuncSetAttribute(gram_mma, cudaFuncAttributeMaxDynamicSharedMemorySize, GRAM_SMEM);
    cudaFuncSetAttribute(gemm_bf,  cudaFuncAttributeMaxDynamicSharedMemorySize, GRAM_SMEM);

    // graph prep + operand conversion
    k_init <<<(NN + 255) / 256, 256>>>();
    k_count<<<(NE + 255) / 256, 256>>>(dst);
    k_scan <<<1, 1024>>>();
    k_dinv <<<(NN + 255) / 256, 256>>>();
    k_fill <<<(NE + 255) / 256, 256>>>(src, dst);
    k_split_h <<<NN, 32>>>((const float4*)h);
    k_split_w1<<<512, 128>>>(W1a, W1s);
    k_split_w2<<<dim3(128, 2), 256>>>(W2a, W2s);

    // layer 1: XW1 = A1' @ WT1'^T  (M=NN, N=512, K=384)
    gemm_bf<<<dim3(4, NT), 256, GRAM_SMEM>>>(pA1, pWT1, 384, pXW1, 512, 0, NN);
    k_agg1<<<NN, 128>>>((const float4*)pXW1, b1a, b1s);

    // layer 2: XW2[:, :128] = A2a' @ WT2a'^T ; XW2[:,128:] = A2s' @ WT2s'^T (K=768)
    gemm_bf<<<dim3(1, NT), 256, GRAM_SMEM>>>(pA2a, pWT2a, 768, pXW2, 256, 0,   NN);
    gemm_bf<<<dim3(1, NT), 256, GRAM_SMEM>>>(pA2s, pWT2s, 768, pXW2, 256, 128, NN);
    k_agg2<<<NN, 64>>>((const float4*)pXW2, out, pHb, b2a, b2s);

    // s_ = h_ @ h_^T via bf16 tensor cores, symmetric (upper tiles only)
    gram_mma<<<NTILES, 256, GRAM_SMEM>>>(pHb, out + S_OFF);

    // h passthrough
    cudaMemcpyAsync(out + H_OFF, h, (size_t)NN * 128 * sizeof(float),
                    cudaMemcpyDeviceToDevice);
}

// round 8
// speedup vs baseline: 3.0070x; 1.0595x over previous
#include <cuda_runtime.h>
#include <cuda_bf16.h>
#include <cstdint>

// Problem constants
#define NN   10000
#define NE   320000
#define IND  128
#define F2   256     // 2*OUT

// Output layout: x_ [NN*128], s_ [NN*NN], h [NN*128]
#define S_OFF  (NN * 128)
#define H_OFF  (S_OFF + (size_t)NN * NN)

// ---------------- static device scratch (no allocs allowed) ----------------
__device__ float g_XW2[NN * F2];              // H1 @ [W2a | W2s] (fp32, gathered by agg2)
__device__ __nv_bfloat16 g_A1 [NN * 384];     // agg(h) split: [hi | lo | hi]    (K=384)
__device__ __nv_bfloat16 g_A2a[NN * 768];     // H1a split: [hi | lo | hi]       (K=768)
__device__ __nv_bfloat16 g_A2s[NN * 768];     // H1s split
__device__ __nv_bfloat16 g_WT1 [512 * 384];   // [W1a|W1s]^T split: [whi | whi | wlo]
__device__ __nv_bfloat16 g_WT2a[128 * 768];   // W2a^T split
__device__ __nv_bfloat16 g_WT2s[128 * 768];   // W2s^T split
__device__ __nv_bfloat16 g_Hb[NN * 256];      // h_ split: cols [0,128)=hi, [128,256)=lo
__device__ float g_dinv[NN];
__device__ int   g_cnt[NN];
__device__ int   g_cur[NN];
__device__ int   g_rowptr[NN + 1];
__device__ int   g_col[NE];

// ---------------- graph preprocessing ----------------
__global__ void k_init() {
    int i = blockIdx.x * 256 + threadIdx.x;
    if (i < NN) { g_cnt[i] = 0; g_cur[i] = 0; }
}

__global__ void k_count(const int* __restrict__ dst) {
    int e = blockIdx.x * 256 + threadIdx.x;
    if (e < NE) atomicAdd(&g_cnt[dst[e]], 1);
}

__global__ void k_scan() {
    __shared__ int s[1024];
    int t = threadIdx.x;
    const int CH = 10;
    int base = t * CH;
    int sum = 0;
    #pragma unroll
    for (int i = 0; i < CH; i++) { int idx = base + i; if (idx < NN) sum += g_cnt[idx]; }
    s[t] = sum;
    __syncthreads();
    for (int off = 1; off < 1024; off <<= 1) {
        int v = (t >= off) ? s[t - off] : 0;
        __syncthreads();
        s[t] += v;
        __syncthreads();
    }
    int run = (t > 0) ? s[t - 1] : 0;
    #pragma unroll
    for (int i = 0; i < CH; i++) {
        int idx = base + i;
        if (idx < NN) { g_rowptr[idx] = run; run += g_cnt[idx]; }
    }
    if (t == 1023) g_rowptr[NN] = s[1023];
}

__global__ void k_dinv() {
    int i = blockIdx.x * 256 + threadIdx.x;
    if (i < NN) g_dinv[i] = rsqrtf(1.0f + (float)g_cnt[i]);   // +1 self loop
}

__global__ void k_fill(const int* __restrict__ src, const int* __restrict__ dst) {
    int e = blockIdx.x * 256 + threadIdx.x;
    if (e < NE) {
        int d = dst[e];
        int pos = g_rowptr[d] + atomicAdd(&g_cur[d], 1);
        g_col[pos] = src[e];
    }
}

// ---------------- split helpers ----------------
struct alignas(8) bf4 { __nv_bfloat162 a, b; };

__device__ __forceinline__ void split4(float4 v, bf4& hv, bf4& lv) {
    __nv_bfloat16 h0 = __float2bfloat16(v.x), h1 = __float2bfloat16(v.y);
    __nv_bfloat16 h2 = __float2bfloat16(v.z), h3 = __float2bfloat16(v.w);
    __nv_bfloat16 l0 = __float2bfloat16(v.x - __bfloat162float(h0));
    __nv_bfloat16 l1 = __float2bfloat16(v.y - __bfloat162float(h1));
    __nv_bfloat16 l2 = __float2bfloat16(v.z - __bfloat162float(h2));
    __nv_bfloat16 l3 = __float2bfloat16(v.w - __bfloat162float(h3));
    hv.a = __nv_bfloat162(h0, h1); hv.b = __nv_bfloat162(h2, h3);
    lv.a = __nv_bfloat162(l0, l1); lv.b = __nv_bfloat162(l2, l3);
}

__device__ __forceinline__ void split2(float v0, float v1, uint32_t& hi, uint32_t& lo) {
    __nv_bfloat16 h0 = __float2bfloat16(v0), h1 = __float2bfloat16(v1);
    __nv_bfloat16 l0 = __float2bfloat16(v0 - __bfloat162float(h0));
    __nv_bfloat16 l1 = __float2bfloat16(v1 - __bfloat162float(h1));
    __nv_bfloat162 hp(h0, h1), lp(l0, l1);
    hi = *(uint32_t*)&hp; lo = *(uint32_t*)&lp;
}

// W1a/W1s [128,256] -> g_WT1 [512, 384]: row n = output feature, [whi | whi | wlo]
__global__ void k_split_w1(const float* __restrict__ W1a, const float* __restrict__ W1s) {
    int n = blockIdx.x;    // 0..511
    int k = threadIdx.x;   // 0..127
    const float* W = (n < 256) ? W1a : W1s;
    int col = n & 255;
    float v = W[k * 256 + col];
    __nv_bfloat16 hi = __float2bfloat16(v);
    __nv_bfloat16 lo = __float2bfloat16(v - __bfloat162float(hi));
    g_WT1[(size_t)n * 384 + k]       = hi;
    g_WT1[(size_t)n * 384 + 128 + k] = hi;
    g_WT1[(size_t)n * 384 + 256 + k] = lo;
}

// W2a/W2s [256,128] -> g_WT2{a,s} [128, 768]
__global__ void k_split_w2(const float* __restrict__ W2a, const float* __restrict__ W2s) {
    int n = blockIdx.x;    // 0..127 output feature
    int k = threadIdx.x;   // 0..255
    const float* W = blockIdx.y ? W2s : W2a;
    __nv_bfloat16* dst = blockIdx.y ? g_WT2s : g_WT2a;
    float v = W[k * 128 + n];
    __nv_bfloat16 hi = __float2bfloat16(v);
    __nv_bfloat16 lo = __float2bfloat16(v - __bfloat162float(hi));
    dst[(size_t)n * 768 + k]       = hi;
    dst[(size_t)n * 768 + 256 + k] = hi;
    dst[(size_t)n * 768 + 512 + k] = lo;
}

// ---------------- layer-1 aggregation of RAW features: hagg = A_norm @ h ----------
// (aggregate-first: agg(h)@W == agg(h@W), 4x less gather traffic)
__global__ void k_agg_h(const float4* __restrict__ h4) {
    int n = blockIdx.x;
    int t = threadIdx.x;   // 32 threads
    float di = g_dinv[n];
    float4 x = h4[(size_t)n * 32 + t];
    float w0 = di * di;
    float4 acc = make_float4(x.x * w0, x.y * w0, x.z * w0, x.w * w0);

    int e0 = g_rowptr[n], e1 = g_rowptr[n + 1];
    for (int e = e0; e < e1; e++) {
        int s = g_col[e];
        float ws = g_dinv[s] * di;
        float4 v = h4[(size_t)s * 32 + t];
        acc.x += v.x * ws; acc.y += v.y * ws;
        acc.z += v.z * ws; acc.w += v.w * ws;
    }
    bf4 hv, lv; split4(acc, hv, lv);
    int c = t * 4;
    *(bf4*)&g_A1[(size_t)n * 384 + c]       = hv;
    *(bf4*)&g_A1[(size_t)n * 384 + 128 + c] = lv;
    *(bf4*)&g_A1[(size_t)n * 384 + 256 + c] = hv;
}

// ---------------- GCN aggregation layer 2: x_ (fp32) + h_ (split bf16) ----------
__global__ void k_agg2(const float4* __restrict__ XW4,   // [NN][64] float4 (F2=256)
                       float* __restrict__ xout,          // [NN][128]
                       __nv_bfloat16* __restrict__ Hb,    // [NN][256] hi|lo
                       const float* __restrict__ b2a, const float* __restrict__ b2s)
{
    int n = blockIdx.x;
    int t = threadIdx.x;   // 64 threads
    float di = g_dinv[n];
    float4 x = XW4[(size_t)n * 64 + t];
    float w0 = di * di;
    float4 acc = make_float4(x.x * w0, x.y * w0, x.z * w0, x.w * w0);

    int e0 = g_rowptr[n], e1 = g_rowptr[n + 1];
    for (int e = e0; e < e1; e++) {
        int s = g_col[e];
        float ws = g_dinv[s] * di;
        float4 v = XW4[(size_t)s * 64 + t];
        acc.x += v.x * ws; acc.y += v.y * ws;
        acc.z += v.z * ws; acc.w += v.w * ws;
    }

    int c = t * 4;
    if (c < 128) {
        float4 bv = *(const float4*)&b2a[c];
        acc.x += bv.x; acc.y += bv.y; acc.z += bv.z; acc.w += bv.w;
        *(float4*)&xout[(size_t)n * 128 + c] = acc;
    } else {
        int cc = c - 128;
        float4 bv = *(const float4*)&b2s[cc];
        acc.x += bv.x; acc.y += bv.y; acc.z += bv.z; acc.w += bv.w;
        bf4 hv, lv; split4(acc, hv, lv);
        *(bf4*)&Hb[(size_t)n * 256 + cc]       = hv;
        *(bf4*)&Hb[(size_t)n * 256 + 128 + cc] = lv;
    }
}

// ---------------- bf16 tensor-core GEMM: C[M,N] = A[M,K] @ B[N,K]^T ----------------
// MODE 0: plain fp32 store to C.
// MODE 1: bias + relu + bf16 [hi|lo|hi] split-write into g_A2a (cols<256) / g_A2s.
#define BK 32
#define SP 40                       // smem row pitch in bf16 (80B)
#define STG_ELE (128 * SP)
#define GRAM_SMEM (3 * 2 * STG_ELE * 2)   // 61440 bytes

template <int MODE>
__global__ void __launch_bounds__(256, 2)
gemm_bf(const __nv_bfloat16* __restrict__ A, const __nv_bfloat16* __restrict__ B,
        int K, float* __restrict__ C, int ldc, int coff, int M,
        const float* __restrict__ bias_a, const float* __restrict__ bias_s)
{
    extern __shared__ __align__(16) __nv_bfloat16 smem[];
    __nv_bfloat16* As = smem;
    __nv_bfloat16* Bs = smem + 3 * STG_ELE;

    const int tid  = threadIdx.x;
    const int m0   = blockIdx.y * 128;
    const int n0   = blockIdx.x * 128;
    const int w    = tid >> 5;
    const int lane = tid & 31;
    const int wm   = w >> 2;
    const int wn   = w & 3;
    const int nch  = K / BK;

    float acc[4][4][4];
    #pragma unroll
    for (int mt = 0; mt < 4; mt++)
        #pragma unroll
        for (int nt = 0; nt < 4; nt++)
            #pragma unroll
            for (int i = 0; i < 4; i++) acc[mt][nt][i] = 0.0f;

    auto load_stage = [&](int kc, int st) {
        #pragma unroll
        for (int i = 0; i < 2; i++) {
            int c = tid + i * 256;
            int r = c >> 2, q = c & 3;
            {
                int grow = m0 + r;
                int rg = grow < M ? grow : M - 1;
                const __nv_bfloat16* src = A + (size_t)rg * K + kc * BK + q * 8;
                uint32_t dst = (uint32_t)__cvta_generic_to_shared(&As[st * STG_ELE + r * SP + q * 8]);
                asm volatile("cp.async.cg.shared.global [%0], [%1], 16;\n"
                             :: "r"(dst), "l"(src));
            }
            {
                const __nv_bfloat16* src = B + (size_t)(n0 + r) * K + kc * BK + q * 8;
                uint32_t dst = (uint32_t)__cvta_generic_to_shared(&Bs[st * STG_ELE + r * SP + q * 8]);
                asm volatile("cp.async.cg.shared.global [%0], [%1], 16;\n"
                             :: "r"(dst), "l"(src));
            }
        }
    };

    auto compute = [&](int st) {
        #pragma unroll
        for (int ks = 0; ks < 2; ks++) {
            uint32_t a[4][4];
            #pragma unroll
            for (int mt = 0; mt < 4; mt++) {
                int row = wm * 64 + mt * 16 + (lane & 15);
                int col = ks * 16 + ((lane >> 4) << 3);
                uint32_t ad = (uint32_t)__cvta_generic_to_shared(&As[st * STG_ELE + row * SP + col]);
                asm volatile("ldmatrix.sync.aligned.m8n8.x4.shared.b16 {%0,%1,%2,%3}, [%4];"
                             : "=r"(a[mt][0]), "=r"(a[mt][1]), "=r"(a[mt][2]), "=r"(a[mt][3])
                             : "r"(ad));
            }
            uint32_t b[2][4];
            #pragma unroll
            for (int p = 0; p < 2; p++) {
                int j = lane >> 3, l = lane & 7;
                int row = wn * 32 + p * 16 + ((j >> 1) << 3) + l;
                int col = ks * 16 + ((j & 1) << 3);
                uint32_t bd = (uint32_t)__cvta_generic_to_shared(&Bs[st * STG_ELE + row * SP + col]);
                asm volatile("ldmatrix.sync.aligned.m8n8.x4.shared.b16 {%0,%1,%2,%3}, [%4];"
                             : "=r"(b[p][0]), "=r"(b[p][1]), "=r"(b[p][2]), "=r"(b[p][3])
                             : "r"(bd));
            }
            #pragma unroll
            for (int mt = 0; mt < 4; mt++)
                #pragma unroll
                for (int nt = 0; nt < 4; nt++) {
                    uint32_t b0 = b[nt >> 1][(nt & 1) * 2];
                    uint32_t b1 = b[nt >> 1][(nt & 1) * 2 + 1];
                    asm volatile(
                        "mma.sync.aligned.m16n8k16.row.col.f32.bf16.bf16.f32 "
                        "{%0,%1,%2,%3}, {%4,%5,%6,%7}, {%8,%9}, {%0,%1,%2,%3};"
                        : "+f"(acc[mt][nt][0]), "+f"(acc[mt][nt][1]),
                          "+f"(acc[mt][nt][2]), "+f"(acc[mt][nt][3])
                        : "r"(a[mt][0]), "r"(a[mt][1]), "r"(a[mt][2]), "r"(a[mt][3]),
                          "r"(b0), "r"(b1));
                }
        }
    };

    load_stage(0, 0);
    asm volatile("cp.async.commit_group;");
    load_stage(1, 1);
    asm volatile("cp.async.commit_group;");

    #pragma unroll 1
    for (int kc = 0; kc < nch; kc++) {
        asm volatile("cp.async.wait_group 1;");
        __syncthreads();
        if (kc + 2 < nch) {
            load_stage(kc + 2, (kc + 2) % 3);
            asm volatile("cp.async.commit_group;");
        } else {
            asm volatile("cp.async.commit_group;");
        }
        compute(kc % 3);
    }

    #pragma unroll
    for (int mt = 0; mt < 4; mt++)
        #pragma unroll
        for (int nt = 0; nt < 4; nt++) {
            int row = m0 + wm * 64 + mt * 16 + (lane >> 2);
            int col = n0 + wn * 32 + nt * 8 + (lane & 3) * 2;
            if (MODE == 0) {
                if (row < M)
                    *(float2*)&C[(size_t)row * ldc + coff + col] =
                        make_float2(acc[mt][nt][0], acc[mt][nt][1]);
                if (row + 8 < M)
                    *(float2*)&C[(size_t)(row + 8) * ldc + coff + col] =
                        make_float2(acc[mt][nt][2], acc[mt][nt][3]);
            } else {
                // bias + relu + split [hi|lo|hi] into g_A2a / g_A2s
                const float* bias = (col < 256) ? bias_a : bias_s;
                __nv_bfloat16* dst = (col < 256) ? g_A2a : g_A2s;
                int lc = col & 255;
                float bv0 = bias[lc], bv1 = bias[lc + 1];
                #pragma unroll
                for (int half = 0; half < 2; half++) {
                    int r = row + half * 8;
                    if (r < M) {
                        float v0 = fmaxf(acc[mt][nt][half * 2]     + bv0, 0.f);
                        float v1 = fmaxf(acc[mt][nt][half * 2 + 1] + bv1, 0.f);
                        uint32_t hi, lo; split2(v0, v1, hi, lo);
                        uint32_t* p = (uint32_t*)&dst[(size_t)r * 768 + lc];
                        p[0]   = hi;
                        *(uint32_t*)&dst[(size_t)r * 768 + 256 + lc] = lo;
                        *(uint32_t*)&dst[(size_t)r * 768 + 512 + lc] = hi;
                    }
                }
            }
        }
}

// ---------------- Gram via bf16 tensor cores (mma.sync), SYMMETRIC ----------------
#define NT 79
#define NTILES (NT * (NT + 1) / 2)  // 3160
#define TP 66                       // transpose staging pitch (floats)

__global__ void __launch_bounds__(256, 2)
gram_mma(const __nv_bfloat16* __restrict__ Hb, float* __restrict__ C)
{
    extern __shared__ __align__(16) __nv_bfloat16 smem[];
    __nv_bfloat16* As = smem;
    __nv_bfloat16* Bs = smem + 3 * STG_ELE;
    float* sT = (float*)smem;

    int t = blockIdx.x;
    int ti = (int)((2.0f * NT + 1.0f -
                    sqrtf((2.0f * NT + 1.0f) * (2.0f * NT + 1.0f) - 8.0f * (float)t)) * 0.5f);
    if (ti < 0) ti = 0;
    if (ti > NT - 1) ti = NT - 1;
    #pragma unroll 1
    while (ti > 0 && (ti * NT - ti * (ti - 1) / 2) > t) ti--;
    #pragma unroll 1
    while (ti < NT - 1 && ((ti + 1) * NT - (ti + 1) * ti / 2) <= t) ti++;
    const int tj = ti + (t - (ti * NT - ti * (ti - 1) / 2));

    const int m0 = ti * 128;
    const int n0 = tj * 128;

    const int tid  = threadIdx.x;
    const int w    = tid >> 5;
    const int lane = tid & 31;
    const int wm   = w >> 2;
    const int wn   = w & 3;

    float acc[4][4][4];
    #pragma unroll
    for (int mt = 0; mt < 4; mt++)
        #pragma unroll
        for (int nt = 0; nt < 4; nt++)
            #pragma unroll
            for (int i = 0; i < 4; i++) acc[mt][nt][i] = 0.0f;

    auto load_stage = [&](int kc, int st) {
        #pragma unroll
        for (int i = 0; i < 2; i++) {
            int c = tid + i * 256;
            int r = c >> 2, q = c & 3;
            {
                int grow = m0 + r;
                int rg = grow < NN ? grow : NN - 1;
                const __nv_bfloat16* src = Hb + (size_t)rg * 256 + kc * BK + q * 8;
                uint32_t dst = (uint32_t)__cvta_generic_to_shared(&As[st * STG_ELE + r * SP + q * 8]);
                asm volatile("cp.async.cg.shared.global [%0], [%1], 16;\n"
                             :: "r"(dst), "l"(src));
            }
            {
                int grow = n0 + r;
                int rg = grow < NN ? grow : NN - 1;
                const __nv_bfloat16* src = Hb + (size_t)rg * 256 + kc * BK + q * 8;
                uint32_t dst = (uint32_t)__cvta_generic_to_shared(&Bs[st * STG_ELE + r * SP + q * 8]);
                asm volatile("cp.async.cg.shared.global [%0], [%1], 16;\n"
                             :: "r"(dst), "l"(src));
            }
        }
    };

    auto compute = [&](int st) {
        #pragma unroll
        for (int ks = 0; ks < 2; ks++) {
            uint32_t a[4][4];
            #pragma unroll
            for (int mt = 0; mt < 4; mt++) {
                int row = wm * 64 + mt * 16 + (lane & 15);
                int col = ks * 16 + ((lane >> 4) << 3);
                uint32_t ad = (uint32_t)__cvta_generic_to_shared(&As[st * STG_ELE + row * SP + col]);
                asm volatile("ldmatrix.sync.aligned.m8n8.x4.shared.b16 {%0,%1,%2,%3}, [%4];"
                             : "=r"(a[mt][0]), "=r"(a[mt][1]), "=r"(a[mt][2]), "=r"(a[mt][3])
                             : "r"(ad));
            }
            uint32_t b[2][4];
            #pragma unroll
            for (int p = 0; p < 2; p++) {
                int j = lane >> 3, l = lane & 7;
                int row = wn * 32 + p * 16 + ((j >> 1) << 3) + l;
                int col = ks * 16 + ((j & 1) << 3);
                uint32_t bd = (uint32_t)__cvta_generic_to_shared(&Bs[st * STG_ELE + row * SP + col]);
                asm volatile("ldmatrix.sync.aligned.m8n8.x4.shared.b16 {%0,%1,%2,%3}, [%4];"
                             : "=r"(b[p][0]), "=r"(b[p][1]), "=r"(b[p][2]), "=r"(b[p][3])
                             : "r"(bd));
            }
            #pragma unroll
            for (int mt = 0; mt < 4; mt++)
                #pragma unroll
                for (int nt = 0; nt < 4; nt++) {
                    uint32_t b0 = b[nt >> 1][(nt & 1) * 2];
                    uint32_t b1 = b[nt >> 1][(nt & 1) * 2 + 1];
                    asm volatile(
                        "mma.sync.aligned.m16n8k16.row.col.f32.bf16.bf16.f32 "
                        "{%0,%1,%2,%3}, {%4,%5,%6,%7}, {%8,%9}, {%0,%1,%2,%3};"
                        : "+f"(acc[mt][nt][0]), "+f"(acc[mt][nt][1]),
                          "+f"(acc[mt][nt][2]), "+f"(acc[mt][nt][3])
                        : "r"(a[mt][0]), "r"(a[mt][1]), "r"(a[mt][2]), "r"(a[mt][3]),
                          "r"(b0), "r"(b1));
                }
        }
    };

    load_stage(0, 0);
    asm volatile("cp.async.commit_group;");
    load_stage(1, 1);
    asm volatile("cp.async.commit_group;");

    #pragma unroll 1
    for (int kc = 0; kc < 8; kc++) {
        asm volatile("cp.async.wait_group 1;");
        __syncthreads();
        if (kc + 2 < 8) {
            load_stage(kc + 2, (kc + 2) % 3);
            asm volatile("cp.async.commit_group;");
        } else {
            asm volatile("cp.async.commit_group;");
        }
        compute(kc % 3);
    }

    #pragma unroll
    for (int mt = 0; mt < 4; mt++)
        #pragma unroll
        for (int nt = 0; nt < 4; nt++) {
            int row = m0 + wm * 64 + mt * 16 + (lane >> 2);
            int col = n0 + wn * 32 + nt * 8 + (lane & 3) * 2;
            if (col < NN) {
                if (row < NN)
                    *(float2*)&C[(size_t)row * NN + col] =
                        make_float2(acc[mt][nt][0], acc[mt][nt][1]);
                if (row + 8 < NN)
                    *(float2*)&C[(size_t)(row + 8) * NN + col] =
                        make_float2(acc[mt][nt][2], acc[mt][nt][3]);
            }
        }

    if (ti != tj) {
        #pragma unroll
        for (int h = 0; h < 2; h++) {
            __syncthreads();
            if (wm == h) {
                #pragma unroll
                for (int mt = 0; mt < 4; mt++) {
                    int rloc = mt * 16 + (lane >> 2);
                    #pragma unroll
                    for (int nt = 0; nt < 4; nt++) {
                        int cloc = wn * 32 + nt * 8 + (lane & 3) * 2;
                        sT[(cloc)     * TP + rloc]     = acc[mt][nt][0];
                        sT[(cloc + 1) * TP + rloc]     = acc[mt][nt][1];
                        sT[(cloc)     * TP + rloc + 8] = acc[mt][nt][2];
                        sT[(cloc + 1) * TP + rloc + 8] = acc[mt][nt][3];
                    }
                }
            }
            __syncthreads();
            #pragma unroll
            for (int e = 0; e < 8; e++) {
                int idx = tid + 256 * e;
                int cc  = idx >> 4;
                int rr  = (idx & 15) * 4;
                int grow = n0 + cc;
                int gcol = m0 + h * 64 + rr;
                if (grow < NN) {
                    float4 v = make_float4(sT[cc * TP + rr],
                                           sT[cc * TP + rr + 1],
                                           sT[cc * TP + rr + 2],
                                           sT[cc * TP + rr + 3]);
                    if (gcol + 3 < NN) {
                        *(float4*)&C[(size_t)grow * NN + gcol] = v;
                    } else {
                        float vv[4] = {v.x, v.y, v.z, v.w};
                        #pragma unroll
                        for (int k = 0; k < 4; k++)
                            if (gcol + k < NN) C[(size_t)grow * NN + gcol + k] = vv[k];
                    }
                }
            }
        }
    }
}

// ---------------- launcher ----------------
extern "C" void kernel_launch(void* const* d_in, const int* in_sizes, int n_in,
                              void* d_out, int out_size)
{
    const float* h   = (const float*)d_in[0];
    const float* W1a = (const float*)d_in[1];
    const float* b1a = (const float*)d_in[2];
    const float* W2a = (const float*)d_in[3];
    const float* b2a = (const float*)d_in[4];
    const float* W1s = (const float*)d_in[5];
    const float* b1s = (const float*)d_in[6];
    const float* W2s = (const float*)d_in[7];
    const float* b2s = (const float*)d_in[8];
    const int*   ei  = (const int*)d_in[9];
    const int* src = ei;
    const int* dst = ei + NE;
    float* out = (float*)d_out;

    float* pXW2;
    __nv_bfloat16 *pHb, *pA1, *pA2a, *pA2s, *pWT1, *pWT2a, *pWT2s;
    cudaGetSymbolAddress((void**)&pXW2,  g_XW2);
    cudaGetSymbolAddress((void**)&pHb,   g_Hb);
    cudaGetSymbolAddress((void**)&pA1,   g_A1);
    cudaGetSymbolAddress((void**)&pA2a,  g_A2a);
    cudaGetSymbolAddress((void**)&pA2s,  g_A2s);
    cudaGetSymbolAddress((void**)&pWT1,  g_WT1);
    cudaGetSymbolAddress((void**)&pWT2a, g_WT2a);
    cudaGetSymbolAddress((void**)&pWT2s, g_WT2s);

    cudaFuncSetAttribute(gram_mma,   cudaFuncAttributeMaxDynamicSharedMemorySize, GRAM_SMEM);
    cudaFuncSetAttribute(gemm_bf<0>, cudaFuncAttributeMaxDynamicSharedMemorySize, GRAM_SMEM);
    cudaFuncSetAttribute(gemm_bf<1>, cudaFuncAttributeMaxDynamicSharedMemorySize, GRAM_SMEM);

    // graph prep + weight conversion
    k_init <<<(NN + 255) / 256, 256>>>();
    k_count<<<(NE + 255) / 256, 256>>>(dst);
    k_scan <<<1, 1024>>>();
    k_dinv <<<(NN + 255) / 256, 256>>>();
    k_fill <<<(NE + 255) / 256, 256>>>(src, dst);
    k_split_w1<<<512, 128>>>(W1a, W1s);
    k_split_w2<<<dim3(128, 2), 256>>>(W2a, W2s);

    // layer 1 (aggregate-first): hagg = A_norm@h -> A1; H1 = relu(hagg@W1+b) -> A2a/A2s
    k_agg_h<<<NN, 32>>>((const float4*)h);
    gemm_bf<1><<<dim3(4, NT), 256, GRAM_SMEM>>>(pA1, pWT1, 384, nullptr, 0, 0, NN, b1a, b1s);

    // layer 2 (transform-first): XW2 = H1 @ W2 -> fp32; then aggregate
    gemm_bf<0><<<dim3(1, NT), 256, GRAM_SMEM>>>(pA2a, pWT2a, 768, pXW2, 256, 0,   NN, nullptr, nullptr);
    gemm_bf<0><<<dim3(1, NT), 256, GRAM_SMEM>>>(pA2s, pWT2s, 768, pXW2, 256, 128, NN, nullptr, nullptr);
    k_agg2<<<NN, 64>>>((const float4*)pXW2, out, pHb, b2a, b2s);

    // s_ = h_ @ h_^T via bf16 tensor cores, symmetric (upper tiles only)
    gram_mma<<<NTILES, 256, GRAM_SMEM>>>(pHb, out + S_OFF);

    // h passthrough
    cudaMemcpyAsync(out + H_OFF, h, (size_t)NN * 128 * sizeof(float),
                    cudaMemcpyDeviceToDevice);
}